// round 5
// baseline (speedup 1.0000x reference)
#include <cuda_runtime.h>
#include <cuda_bf16.h>
#include <math.h>

// Problem constants
#define BB   32
#define SS   512
#define DD   1024
#define EE   4096          // 4*D
#define NBLK 128           // recurrence CTAs (all co-resident: <=148 SMs, 1 CTA/SM)

typedef unsigned long long u64;

// ---------- packed f32x2 helpers (FFMA2: 2x fp32 throughput, PTX-only) ----------
__device__ __forceinline__ u64 pk2(float x, float y) {
    u64 r; asm("mov.b64 %0, {%1, %2};" : "=l"(r) : "f"(x), "f"(y)); return r;
}
__device__ __forceinline__ u64 fma2(u64 a, u64 b, u64 c) {
    u64 d; asm("fma.rn.f32x2 %0, %1, %2, %3;" : "=l"(d) : "l"(a), "l"(b), "l"(c)); return d;
}
__device__ __forceinline__ u64 add2(u64 a, u64 b) {
    u64 d; asm("add.rn.f32x2 %0, %1, %2;" : "=l"(d) : "l"(a), "l"(b)); return d;
}
__device__ __forceinline__ float2 upk(u64 v) {
    float2 f; asm("mov.b64 {%0, %1}, %2;" : "=f"(f.x), "=f"(f.y) : "l"(v)); return f;
}

// ---------- scratch (static __device__: no runtime allocation) ----------
__device__ __align__(16) float g_xp[(size_t)SS * BB * EE];  // x_proj, [s][b][e], 268MB
__device__ __align__(16) float g_hT[DD * BB];               // h transposed [d][b]
__device__ u64 g_bar;                                       // grid barrier counter (monotonic)

// =====================================================================
// Kernel 1: x_proj[s][b][e] = sum_k x[b][s][k] * Ucat[k][e] + bcat[e]
// GEMM M=16384 (m=b*512+s), N=4096, K=1024. Tile 64x128, kc=16.
// 256 threads, each 4m x 8n outputs via f32x2.
// =====================================================================
__global__ void __launch_bounds__(256) xproj_kernel(
    const float* __restrict__ X,
    const float* __restrict__ Ui, const float* __restrict__ Uf,
    const float* __restrict__ Uo, const float* __restrict__ Ug,
    const float* __restrict__ bi, const float* __restrict__ bf,
    const float* __restrict__ bo, const float* __restrict__ bg)
{
    __shared__ float As[16 * 68];    // [k][m], padded row 68
    __shared__ float Bs[16 * 128];   // [k][n]

    const int tid  = threadIdx.x;
    const int n0   = blockIdx.x * 128;   // 4096/128 = 32 tiles, never straddles a gate
    const int m0   = blockIdx.y * 64;
    const int gate = n0 >> 10;
    const int col0 = n0 & 1023;

    const float* Up = (gate == 0) ? Ui : (gate == 1) ? Uf : (gate == 2) ? Uo : Ug;
    const float* bp = (gate == 0) ? bi : (gate == 1) ? bf : (gate == 2) ? bo : bg;

    const int tm = tid & 15;      // m group (4 rows each)
    const int tn = tid >> 4;      // n group (8 cols each)
    const int arow = tid >> 2, akq = tid & 3;   // A tile load
    const int brow = tid >> 5, bc4 = tid & 31;  // B tile load

    u64 acc[4][4];
    #pragma unroll
    for (int i = 0; i < 4; i++)
        #pragma unroll
        for (int p = 0; p < 4; p++) acc[i][p] = 0ULL;

    for (int kc = 0; kc < 1024; kc += 16) {
        float4 av  = *(const float4*)&X[(size_t)(m0 + arow) * 1024 + kc + akq * 4];
        float4 bv0 = *(const float4*)&Up[(size_t)(kc + brow) * 1024 + col0 + bc4 * 4];
        float4 bv1 = *(const float4*)&Up[(size_t)(kc + 8 + brow) * 1024 + col0 + bc4 * 4];
        __syncthreads();
        As[(akq * 4 + 0) * 68 + arow] = av.x;
        As[(akq * 4 + 1) * 68 + arow] = av.y;
        As[(akq * 4 + 2) * 68 + arow] = av.z;
        As[(akq * 4 + 3) * 68 + arow] = av.w;
        *(float4*)&Bs[brow * 128 + bc4 * 4]       = bv0;
        *(float4*)&Bs[(brow + 8) * 128 + bc4 * 4] = bv1;
        __syncthreads();

        #pragma unroll
        for (int kk = 0; kk < 16; kk++) {
            float4 a4 = *(float4*)&As[kk * 68 + tm * 4];
            ulonglong2 w01 = *(ulonglong2*)&Bs[kk * 128 + tn * 8];
            ulonglong2 w23 = *(ulonglong2*)&Bs[kk * 128 + tn * 8 + 4];
            u64 ax0 = pk2(a4.x, a4.x), ax1 = pk2(a4.y, a4.y);
            u64 ax2 = pk2(a4.z, a4.z), ax3 = pk2(a4.w, a4.w);
            acc[0][0] = fma2(ax0, w01.x, acc[0][0]);
            acc[0][1] = fma2(ax0, w01.y, acc[0][1]);
            acc[0][2] = fma2(ax0, w23.x, acc[0][2]);
            acc[0][3] = fma2(ax0, w23.y, acc[0][3]);
            acc[1][0] = fma2(ax1, w01.x, acc[1][0]);
            acc[1][1] = fma2(ax1, w01.y, acc[1][1]);
            acc[1][2] = fma2(ax1, w23.x, acc[1][2]);
            acc[1][3] = fma2(ax1, w23.y, acc[1][3]);
            acc[2][0] = fma2(ax2, w01.x, acc[2][0]);
            acc[2][1] = fma2(ax2, w01.y, acc[2][1]);
            acc[2][2] = fma2(ax2, w23.x, acc[2][2]);
            acc[2][3] = fma2(ax2, w23.y, acc[2][3]);
            acc[3][0] = fma2(ax3, w01.x, acc[3][0]);
            acc[3][1] = fma2(ax3, w01.y, acc[3][1]);
            acc[3][2] = fma2(ax3, w23.x, acc[3][2]);
            acc[3][3] = fma2(ax3, w23.y, acc[3][3]);
        }
    }

    float bvv[8];
    #pragma unroll
    for (int c = 0; c < 8; c++) bvv[c] = bp[col0 + tn * 8 + c];

    #pragma unroll
    for (int i = 0; i < 4; i++) {
        int m = m0 + tm * 4 + i;
        int s = m & 511, b = m >> 9;
        float* dst = &g_xp[((size_t)s * BB + b) * EE + n0 + tn * 8];
        float2 p0 = upk(acc[i][0]), p1 = upk(acc[i][1]);
        float2 p2 = upk(acc[i][2]), p3 = upk(acc[i][3]);
        float4 o0 = {p0.x + bvv[0], p0.y + bvv[1], p1.x + bvv[2], p1.y + bvv[3]};
        float4 o1 = {p2.x + bvv[4], p2.y + bvv[5], p3.x + bvv[6], p3.y + bvv[7]};
        *(float4*)dst       = o0;
        *(float4*)(dst + 4) = o1;
    }
}

// =====================================================================
// Kernel 2: persistent recurrence. 128 CTAs x 256 threads.
// CTA n owns d-cols [n*8, n*8+8) -> 32 z-cols (4 gates x 8), W-slice in SMEM.
// 4-way K-split (groups of 64 threads), manual grid barrier per step.
// SMEM: Ws 32768f + shH 8192f + shRed 3072f + shZ 1024f = 45056 floats = 180224 B
// =====================================================================
#define REC_SMEM_BYTES (45056 * 4)

__global__ void __launch_bounds__(256, 1) lstm_rec_kernel(
    const float* __restrict__ Wi, const float* __restrict__ Wf,
    const float* __restrict__ Wo, const float* __restrict__ Wg,
    float* __restrict__ out)
{
    extern __shared__ float sm[];
    float* Ws   = sm;                      // [1024][32], j = gate*8+jj
    float* shH  = sm + 32768;              // [4 groups][64 k][32 b]
    u64*   shRed = (u64*)(sm + 40960);     // 3 * 512 u64
    float* shZ  = sm + 44032;              // [32 b][32 j]

    const int tid = threadIdx.x;
    const int d0  = blockIdx.x * 8;

    // Load persistent W slice: Ws[k*32 + gate*8 + jj] = Wgate[k][d0+jj]
    {
        const float* Wm[4] = {Wi, Wf, Wo, Wg};
        for (int idx = tid; idx < 32768; idx += 256) {
            int k = idx >> 5, j = idx & 31;
            Ws[idx] = Wm[j >> 3][(size_t)k * 1024 + d0 + (j & 7)];
        }
    }
    // Zero this CTA's h slice (re-done every launch -> deterministic across replays)
    {
        int dd = tid >> 5, b = tid & 31;   // 8 x 32 = 256
        g_hT[(d0 + dd) * 32 + b] = 0.0f;
    }
    float c_reg = 0.0f;
    const int eb = tid >> 3;  // elementwise batch 0..31
    const int ed = tid & 7;   // elementwise d offset 0..7

    __threadfence();
    __syncthreads();

    // ---- grid barrier #0 (derive epoch base from monotonic counter) ----
    u64 bar_target = 0;
    if (tid == 0) {
        u64 old = atomicAdd(&g_bar, 1ULL);
        u64 base = old - (old & (u64)(NBLK - 1));
        bar_target = base + NBLK;
        while (*((volatile u64*)&g_bar) < bar_target) { }
        __threadfence();
    }
    __syncthreads();

    const int grp = tid >> 6;        // 0..3 : K-split group
    const int lt  = tid & 63;
    const int tb  = lt & 15;         // b-pair 0..15
    const int tj  = lt >> 4;         // 0..3 == gate; j = tj*8 + jj
    const int b0  = tb * 2;
    const int kbase = grp * 256;
    float* myH = shH + grp * 2048;   // [64][32]

    for (int s = 0; s < SS; s++) {
        // Prefetch this thread's x_proj contribution (group 0 only consumes it)
        const float* xps = g_xp + (size_t)s * BB * EE;
        float4 xa0, xa1, xb0, xb1;
        if (grp == 0) {
            const float* pb0 = xps + (size_t)b0 * EE + tj * 1024 + d0;
            const float* pb1 = xps + (size_t)(b0 + 1) * EE + tj * 1024 + d0;
            xa0 = *(const float4*)pb0;       xa1 = *(const float4*)(pb0 + 4);
            xb0 = *(const float4*)pb1;       xb1 = *(const float4*)(pb1 + 4);
        }

        u64 a00 = 0, a01 = 0, a02 = 0, a03 = 0;
        u64 a10 = 0, a11 = 0, a12 = 0, a13 = 0;

        for (int ch = 0; ch < 4; ch++) {
            __syncthreads();
            // stage 64 k-rows of h^T for this group (L2 -> SMEM, bypass L1)
            {
                const float4* src = (const float4*)(g_hT + (kbase + ch * 64) * 32);
                float4* dst4 = (float4*)myH;
                for (int q = lt; q < 512; q += 64) dst4[q] = __ldcg(src + q);
            }
            __syncthreads();

            #pragma unroll 8
            for (int kk = 0; kk < 64; kk++) {
                int gk = kbase + ch * 64 + kk;
                float2 hv = *(float2*)&myH[kk * 32 + b0];
                ulonglong2 w01 = *(ulonglong2*)&Ws[gk * 32 + tj * 8];
                ulonglong2 w23 = *(ulonglong2*)&Ws[gk * 32 + tj * 8 + 4];
                u64 hx = pk2(hv.x, hv.x), hy = pk2(hv.y, hv.y);
                a00 = fma2(hx, w01.x, a00);  a01 = fma2(hx, w01.y, a01);
                a02 = fma2(hx, w23.x, a02);  a03 = fma2(hx, w23.y, a03);
                a10 = fma2(hy, w01.x, a10);  a11 = fma2(hy, w01.y, a11);
                a12 = fma2(hy, w23.x, a12);  a13 = fma2(hy, w23.y, a13);
            }
        }

        // ---- K-split reduction ----
        if (grp > 0) {
            u64* r = shRed + (size_t)(grp - 1) * 512 + lt * 8;
            r[0] = a00; r[1] = a01; r[2] = a02; r[3] = a03;
            r[4] = a10; r[5] = a11; r[6] = a12; r[7] = a13;
        }
        __syncthreads();
        if (grp == 0) {
            #pragma unroll
            for (int g2 = 0; g2 < 3; g2++) {
                u64* r = shRed + (size_t)g2 * 512 + lt * 8;
                a00 = add2(a00, r[0]); a01 = add2(a01, r[1]);
                a02 = add2(a02, r[2]); a03 = add2(a03, r[3]);
                a10 = add2(a10, r[4]); a11 = add2(a11, r[5]);
                a12 = add2(a12, r[6]); a13 = add2(a13, r[7]);
            }
            float2 p00 = upk(a00), p01 = upk(a01), p02 = upk(a02), p03 = upk(a03);
            float2 p10 = upk(a10), p11 = upk(a11), p12 = upk(a12), p13 = upk(a13);
            float4 z00 = {p00.x + xa0.x, p00.y + xa0.y, p01.x + xa0.z, p01.y + xa0.w};
            float4 z01 = {p02.x + xa1.x, p02.y + xa1.y, p03.x + xa1.z, p03.y + xa1.w};
            float4 z10 = {p10.x + xb0.x, p10.y + xb0.y, p11.x + xb0.z, p11.y + xb0.w};
            float4 z11 = {p12.x + xb1.x, p12.y + xb1.y, p13.x + xb1.z, p13.y + xb1.w};
            *(float4*)&shZ[b0 * 32 + tj * 8]           = z00;
            *(float4*)&shZ[b0 * 32 + tj * 8 + 4]       = z01;
            *(float4*)&shZ[(b0 + 1) * 32 + tj * 8]     = z10;
            *(float4*)&shZ[(b0 + 1) * 32 + tj * 8 + 4] = z11;
        }
        __syncthreads();

        // ---- elementwise gates: one (b, d) per thread ----
        {
            float zi = shZ[eb * 32 + ed];
            float zf = shZ[eb * 32 + 8 + ed];
            float zo = shZ[eb * 32 + 16 + ed];
            float zg = shZ[eb * 32 + 24 + ed];
            float it = 1.0f / (1.0f + expf(-zi));
            float ft = 1.0f / (1.0f + expf(-zf));
            float ot = 1.0f / (1.0f + expf(-zo));
            float gt = tanhf(zg);
            float cc = ft * c_reg + it * gt;
            float ct = 1.0f / (1.0f + expf(-cc));   // nonstandard cell (matches reference)
            float ht = tanhf(ct) * ot;
            c_reg = ct;
            g_hT[(d0 + ed) * 32 + eb] = ht;
            out[((size_t)eb * SS + s) * DD + d0 + ed] = ht;
        }

        // ---- grid barrier per step ----
        __threadfence();
        __syncthreads();
        if (tid == 0) {
            atomicAdd(&g_bar, 1ULL);
            bar_target += NBLK;
            while (*((volatile u64*)&g_bar) < bar_target) { }
            __threadfence();
        }
        __syncthreads();
    }
}

// =====================================================================
// Input order (setup_inputs dict): 0:seq, 1:Ui, 2:Wi, 3:Uf, 4:Wf,
// 5:Uo, 6:Wo, 7:Ug, 8:Wg, 9:bi, 10:bf, 11:bo, 12:bg
// =====================================================================
extern "C" void kernel_launch(void* const* d_in, const int* in_sizes, int n_in,
                              void* d_out, int out_size)
{
    const float* X  = (const float*)d_in[0];
    const float* Ui = (const float*)d_in[1];
    const float* Wi = (const float*)d_in[2];
    const float* Uf = (const float*)d_in[3];
    const float* Wf = (const float*)d_in[4];
    const float* Uo = (const float*)d_in[5];
    const float* Wo = (const float*)d_in[6];
    const float* Ug = (const float*)d_in[7];
    const float* Wg = (const float*)d_in[8];
    const float* bi = (const float*)d_in[9];
    const float* bf = (const float*)d_in[10];
    const float* bo = (const float*)d_in[11];
    const float* bg = (const float*)d_in[12];
    float* out = (float*)d_out;

    dim3 g1(EE / 128, (BB * SS) / 64);   // (32, 256)
    xproj_kernel<<<g1, 256>>>(X, Ui, Uf, Uo, Ug, bi, bf, bo, bg);

    cudaFuncSetAttribute(lstm_rec_kernel,
                         cudaFuncAttributeMaxDynamicSharedMemorySize, REC_SMEM_BYTES);
    lstm_rec_kernel<<<NBLK, 256, REC_SMEM_BYTES>>>(Wi, Wf, Wo, Wg, out);
}

// round 7
// speedup vs baseline: 1.2446x; 1.2446x over previous
#include <cuda_runtime.h>
#include <cuda_bf16.h>
#include <math.h>
#include <stdint.h>

// Problem constants
#define BB   32
#define SS   512
#define DD   1024
#define EE   4096          // 4*D
#define NBLK 128           // recurrence CTAs (all co-resident, 1/SM)

typedef unsigned long long u64;

// ---------- packed f32x2 helpers (xproj kernel) ----------
__device__ __forceinline__ u64 pk2(float x, float y) {
    u64 r; asm("mov.b64 %0, {%1, %2};" : "=l"(r) : "f"(x), "f"(y)); return r;
}
__device__ __forceinline__ u64 fma2(u64 a, u64 b, u64 c) {
    u64 d; asm("fma.rn.f32x2 %0, %1, %2, %3;" : "=l"(d) : "l"(a), "l"(b), "l"(c)); return d;
}
__device__ __forceinline__ float2 upk(u64 v) {
    float2 f; asm("mov.b64 {%0, %1}, %2;" : "=f"(f.x), "=f"(f.y) : "l"(v)); return f;
}

// ---------- scratch (static __device__: no runtime allocation) ----------
__device__ __align__(16) float g_xp[(size_t)SS * BB * EE];       // x_proj [s][b][e]
__device__ __align__(16) __nv_bfloat16 g_hHi[BB * DD];           // h hi, [b][d]
__device__ __align__(16) __nv_bfloat16 g_hLo[BB * DD];           // h lo, [b][d]
__device__ u64 g_bar;                                            // grid barrier (monotonic)

__device__ __forceinline__ uint32_t smem_u32(const void* p) {
    uint32_t a;
    asm("{ .reg .u64 t; cvta.to.shared.u64 t, %1; cvt.u32.u64 %0, t; }" : "=r"(a) : "l"(p));
    return a;
}

__device__ __forceinline__ float sigf(float x) {
    float e = __expf(-x);
    float y; asm("rcp.approx.f32 %0, %1;" : "=f"(y) : "f"(1.0f + e));
    return y;
}

__device__ __forceinline__ uint32_t pack_bf2(float a, float b) {
    __nv_bfloat16 h0 = __float2bfloat16(a), h1 = __float2bfloat16(b);
    uint16_t u0, u1;
    memcpy(&u0, &h0, 2); memcpy(&u1, &h1, 2);
    return (uint32_t)u0 | ((uint32_t)u1 << 16);
}

#define LDMATRIX_X4(a0, a1, a2, a3, addr) \
    asm volatile("ldmatrix.sync.aligned.m8n8.x4.shared.b16 {%0,%1,%2,%3}, [%4];" \
                 : "=r"(a0), "=r"(a1), "=r"(a2), "=r"(a3) : "r"(addr))

#define MMA_BF16(c, a0, a1, a2, a3, b0, b1) \
    asm volatile("mma.sync.aligned.m16n8k16.row.col.f32.bf16.bf16.f32 " \
                 "{%0,%1,%2,%3}, {%4,%5,%6,%7}, {%8,%9}, {%0,%1,%2,%3};" \
                 : "+f"((c)[0]), "+f"((c)[1]), "+f"((c)[2]), "+f"((c)[3]) \
                 : "r"(a0), "r"(a1), "r"(a2), "r"(a3), "r"(b0), "r"(b1))

// =====================================================================
// Kernel 1: x_proj (fp32 SIMT GEMM — unchanged, ~2.4ms)
// =====================================================================
__global__ void __launch_bounds__(256) xproj_kernel(
    const float* __restrict__ X,
    const float* __restrict__ Ui, const float* __restrict__ Uf,
    const float* __restrict__ Uo, const float* __restrict__ Ug,
    const float* __restrict__ bi, const float* __restrict__ bf,
    const float* __restrict__ bo, const float* __restrict__ bg)
{
    __shared__ float As[16 * 68];
    __shared__ float Bs[16 * 128];

    const int tid  = threadIdx.x;
    const int n0   = blockIdx.x * 128;
    const int m0   = blockIdx.y * 64;
    const int gate = n0 >> 10;
    const int col0 = n0 & 1023;

    const float* Up = (gate == 0) ? Ui : (gate == 1) ? Uf : (gate == 2) ? Uo : Ug;
    const float* bp = (gate == 0) ? bi : (gate == 1) ? bf : (gate == 2) ? bo : bg;

    const int tm = tid & 15;
    const int tn = tid >> 4;
    const int arow = tid >> 2, akq = tid & 3;
    const int brow = tid >> 5, bc4 = tid & 31;

    u64 acc[4][4];
    #pragma unroll
    for (int i = 0; i < 4; i++)
        #pragma unroll
        for (int p = 0; p < 4; p++) acc[i][p] = 0ULL;

    for (int kc = 0; kc < 1024; kc += 16) {
        float4 av  = *(const float4*)&X[(size_t)(m0 + arow) * 1024 + kc + akq * 4];
        float4 bv0 = *(const float4*)&Up[(size_t)(kc + brow) * 1024 + col0 + bc4 * 4];
        float4 bv1 = *(const float4*)&Up[(size_t)(kc + 8 + brow) * 1024 + col0 + bc4 * 4];
        __syncthreads();
        As[(akq * 4 + 0) * 68 + arow] = av.x;
        As[(akq * 4 + 1) * 68 + arow] = av.y;
        As[(akq * 4 + 2) * 68 + arow] = av.z;
        As[(akq * 4 + 3) * 68 + arow] = av.w;
        *(float4*)&Bs[brow * 128 + bc4 * 4]       = bv0;
        *(float4*)&Bs[(brow + 8) * 128 + bc4 * 4] = bv1;
        __syncthreads();

        #pragma unroll
        for (int kk = 0; kk < 16; kk++) {
            float4 a4 = *(float4*)&As[kk * 68 + tm * 4];
            ulonglong2 w01 = *(ulonglong2*)&Bs[kk * 128 + tn * 8];
            ulonglong2 w23 = *(ulonglong2*)&Bs[kk * 128 + tn * 8 + 4];
            u64 ax0 = pk2(a4.x, a4.x), ax1 = pk2(a4.y, a4.y);
            u64 ax2 = pk2(a4.z, a4.z), ax3 = pk2(a4.w, a4.w);
            acc[0][0] = fma2(ax0, w01.x, acc[0][0]);
            acc[0][1] = fma2(ax0, w01.y, acc[0][1]);
            acc[0][2] = fma2(ax0, w23.x, acc[0][2]);
            acc[0][3] = fma2(ax0, w23.y, acc[0][3]);
            acc[1][0] = fma2(ax1, w01.x, acc[1][0]);
            acc[1][1] = fma2(ax1, w01.y, acc[1][1]);
            acc[1][2] = fma2(ax1, w23.x, acc[1][2]);
            acc[1][3] = fma2(ax1, w23.y, acc[1][3]);
            acc[2][0] = fma2(ax2, w01.x, acc[2][0]);
            acc[2][1] = fma2(ax2, w01.y, acc[2][1]);
            acc[2][2] = fma2(ax2, w23.x, acc[2][2]);
            acc[2][3] = fma2(ax2, w23.y, acc[2][3]);
            acc[3][0] = fma2(ax3, w01.x, acc[3][0]);
            acc[3][1] = fma2(ax3, w01.y, acc[3][1]);
            acc[3][2] = fma2(ax3, w23.x, acc[3][2]);
            acc[3][3] = fma2(ax3, w23.y, acc[3][3]);
        }
    }

    float bvv[8];
    #pragma unroll
    for (int c = 0; c < 8; c++) bvv[c] = bp[col0 + tn * 8 + c];

    #pragma unroll
    for (int i = 0; i < 4; i++) {
        int m = m0 + tm * 4 + i;
        int s = m & 511, b = m >> 9;
        float* dst = &g_xp[((size_t)s * BB + b) * EE + n0 + tn * 8];
        float2 p0 = upk(acc[i][0]), p1 = upk(acc[i][1]);
        float2 p2 = upk(acc[i][2]), p3 = upk(acc[i][3]);
        float4 o0 = {p0.x + bvv[0], p0.y + bvv[1], p1.x + bvv[2], p1.y + bvv[3]};
        float4 o1 = {p2.x + bvv[4], p2.y + bvv[5], p3.x + bvv[6], p3.y + bvv[7]};
        *(float4*)dst       = o0;
        *(float4*)(dst + 4) = o1;
    }
}

// =====================================================================
// Kernel 2: HMMA recurrence. 128 persistent CTAs x 256 threads.
// CTA owns 32 z-cols (gate*8 + dd, dd in [d0, d0+8)). Per step:
//   z[32b][32j] = h[32][1024] @ Wslice[1024][32]  (bf16x3, f32 accum)
// Warp (ks, nh): K-chunk ks*256, N-half nh*16. W frags resident in regs.
// SMEM: h hi [32][1032]bf16 | h lo [32][1032]bf16 | red [4][32][32]f32
// =====================================================================
#define H_STRIDE 1032                       // 2064 B rows: 16B bank skew
#define REC_SMEM_BYTES (2 * 32 * H_STRIDE * 2 + 4 * 32 * 32 * 4)   // 148480

__global__ void __launch_bounds__(256, 1) lstm_rec_mma(
    const float* __restrict__ Wi, const float* __restrict__ Wf,
    const float* __restrict__ Wo, const float* __restrict__ Wg,
    float* __restrict__ out)
{
    extern __shared__ char sm[];
    __nv_bfloat16* sHi = (__nv_bfloat16*)sm;                   // [32][1032]
    __nv_bfloat16* sLo = sHi + 32 * H_STRIDE;
    float* red = (float*)(sm + 2 * 32 * H_STRIDE * 2);         // [4 ks][32 j][32 b]

    const int tid  = threadIdx.x;
    const int wid  = tid >> 5;
    const int lane = tid & 31;
    const int d0   = blockIdx.x * 8;

    const int ks = wid >> 1;          // K-chunk 0..3
    const int nh = wid & 1;           // N-half 0..1
    const int kbase = ks << 8;
    const int lt2 = tid & 63;         // lane within warp-pair

    // ---- W fragments resident in registers (one-time global load) ----
    // B frag layout (m16n8k16 .col): reg r of tile (k16, ni):
    //   k = kbase + k16*16 + (lane&3)*2 + r*8 (+1), n(col j) = nh*16 + ni*8 + lane>>2
    uint32_t BHi[16][2][2], BLo[16][2][2];
    {
        const float* Wm[4] = {Wi, Wf, Wo, Wg};
        #pragma unroll
        for (int k16 = 0; k16 < 16; k16++)
            #pragma unroll
            for (int ni = 0; ni < 2; ni++)
                #pragma unroll
                for (int r = 0; r < 2; r++) {
                    int j = nh * 16 + ni * 8 + (lane >> 2);
                    int k0 = kbase + k16 * 16 + (lane & 3) * 2 + r * 8;
                    const float* wp = Wm[j >> 3] + (size_t)k0 * 1024 + d0 + (j & 7);
                    float w0 = __ldg(wp), w1 = __ldg(wp + 1024);
                    float h0 = __bfloat162float(__float2bfloat16(w0));
                    float h1 = __bfloat162float(__float2bfloat16(w1));
                    BHi[k16][ni][r] = pack_bf2(w0, w1);
                    BLo[k16][ni][r] = pack_bf2(w0 - h0, w1 - h1);
                }
    }

    // ---- zero h slice (fresh every launch -> graph-replay deterministic) ----
    const int gb  = tid & 31;    // gate-phase batch
    const int gdl = tid >> 5;    // gate-phase local d 0..7
    g_hHi[gb * DD + d0 + gdl] = __float2bfloat16(0.0f);
    g_hLo[gb * DD + d0 + gdl] = __float2bfloat16(0.0f);
    float c_reg = 0.0f;

    __threadfence();
    __syncthreads();

    // ---- initial grid barrier ----
    u64 bar_target = 0;
    if (tid == 0) {
        u64 old = atomicAdd(&g_bar, 1ULL);
        u64 bs  = old - (old & (u64)(NBLK - 1));
        bar_target = bs + NBLK;
        while (*((volatile u64*)&g_bar) < bar_target) { }
        __threadfence();
    }
    __syncthreads();

    const uint32_t sHi_u = smem_u32(sHi);
    const uint32_t sLo_u = smem_u32(sLo);

    for (int s = 0; s < SS; s++) {
        // xp prefetch (hide L2 latency across whole step)
        const float* xpp = g_xp + ((size_t)s * BB + gb) * EE + d0 + gdl;
        float xp0 = __ldg(xpp);
        float xp1 = __ldg(xpp + 1024);
        float xp2 = __ldg(xpp + 2048);
        float xp3 = __ldg(xpp + 3072);

        // ---- fill: warp-pair ks stages its own K-chunk (hi+lo), L1-bypass ----
        // 2048 uint4 (hi 1024 + lo 1024) over 64 threads = 32 iters
        #pragma unroll 4
        for (int it = 0; it < 32; it++) {
            int idx = it * 64 + lt2;
            int arr = idx >> 10, rem = idx & 1023;
            int b = rem >> 5, k8 = rem & 31;
            const __nv_bfloat16* src =
                (arr ? g_hLo : g_hHi) + b * DD + kbase + k8 * 8;
            uint4 v = __ldcg((const uint4*)src);
            __nv_bfloat16* dst = (arr ? sLo : sHi) + b * H_STRIDE + kbase + k8 * 8;
            *(uint4*)dst = v;
        }
        // pair-local barrier (ids 1..4), count = 64
        asm volatile("bar.sync %0, 64;" :: "r"(1 + ks) : "memory");

        // ---- MMA: 3 passes (Ahi*Bhi + Alo*Bhi + Ahi*Blo), f32 accum ----
        float c[2][2][4];
        #pragma unroll
        for (int mi = 0; mi < 2; mi++)
            #pragma unroll
            for (int ni = 0; ni < 2; ni++)
                #pragma unroll
                for (int q = 0; q < 4; q++) c[mi][ni][q] = 0.0f;

        #pragma unroll
        for (int pass = 0; pass < 3; pass++) {
            const uint32_t Abase = (pass == 1) ? sLo_u : sHi_u;
            #pragma unroll
            for (int k16 = 0; k16 < 16; k16++) {
                const int kcol = kbase + k16 * 16;
                #pragma unroll
                for (int mi = 0; mi < 2; mi++) {
                    uint32_t a0, a1, a2, a3;
                    uint32_t addr = Abase +
                        (uint32_t)(((mi * 16 + (lane & 15)) * H_STRIDE
                                    + kcol + (lane >> 4) * 8) * 2);
                    LDMATRIX_X4(a0, a1, a2, a3, addr);
                    #pragma unroll
                    for (int ni = 0; ni < 2; ni++) {
                        uint32_t b0 = (pass == 2) ? BLo[k16][ni][0] : BHi[k16][ni][0];
                        uint32_t b1 = (pass == 2) ? BLo[k16][ni][1] : BHi[k16][ni][1];
                        MMA_BF16(c[mi][ni], a0, a1, a2, a3, b0, b1);
                    }
                }
            }
        }

        // ---- store partials: red[ks][j][b] ----
        {
            float* rb = red + ks * 32 * 32;
            #pragma unroll
            for (int mi = 0; mi < 2; mi++)
                #pragma unroll
                for (int ni = 0; ni < 2; ni++) {
                    int row0 = mi * 16 + (lane >> 2);
                    int col0 = nh * 16 + ni * 8 + (lane & 3) * 2;
                    rb[col0 * 32 + row0]           = c[mi][ni][0];
                    rb[(col0 + 1) * 32 + row0]     = c[mi][ni][1];
                    rb[col0 * 32 + row0 + 8]       = c[mi][ni][2];
                    rb[(col0 + 1) * 32 + row0 + 8] = c[mi][ni][3];
                }
        }
        __syncthreads();

        // ---- gates: thread (gb, gdl) reduces 4 K-chunks x 4 gates ----
        {
            float z0 = xp0, z1 = xp1, z2 = xp2, z3 = xp3;
            #pragma unroll
            for (int kk = 0; kk < 4; kk++) {
                const float* rb = red + kk * 1024;
                z0 += rb[(0 * 8 + gdl) * 32 + gb];
                z1 += rb[(1 * 8 + gdl) * 32 + gb];
                z2 += rb[(2 * 8 + gdl) * 32 + gb];
                z3 += rb[(3 * 8 + gdl) * 32 + gb];
            }
            float it = sigf(z0), ft = sigf(z1), ot = sigf(z2);
            float gt = tanhf(z3);
            float ct = sigf(ft * c_reg + it * gt);   // nonstandard cell (matches ref)
            float ht = tanhf(ct) * ot;
            c_reg = ct;
            out[((size_t)gb * SS + s) * DD + d0 + gdl] = ht;
            __nv_bfloat16 hh = __float2bfloat16(ht);
            __nv_bfloat16 hl = __float2bfloat16(ht - __bfloat162float(hh));
            g_hHi[gb * DD + d0 + gdl] = hh;
            g_hLo[gb * DD + d0 + gdl] = hl;
        }

        // ---- grid barrier per step ----
        __threadfence();
        __syncthreads();
        if (tid == 0) {
            atomicAdd(&g_bar, 1ULL);
            bar_target += NBLK;
            while (*((volatile u64*)&g_bar) < bar_target) { }
            __threadfence();
        }
        __syncthreads();
    }
}

// =====================================================================
// Input order: 0:seq, 1:Ui, 2:Wi, 3:Uf, 4:Wf, 5:Uo, 6:Wo, 7:Ug, 8:Wg,
//              9:bi, 10:bf, 11:bo, 12:bg
// =====================================================================
extern "C" void kernel_launch(void* const* d_in, const int* in_sizes, int n_in,
                              void* d_out, int out_size)
{
    const float* X  = (const float*)d_in[0];
    const float* Ui = (const float*)d_in[1];
    const float* Wi = (const float*)d_in[2];
    const float* Uf = (const float*)d_in[3];
    const float* Wf = (const float*)d_in[4];
    const float* Uo = (const float*)d_in[5];
    const float* Wo = (const float*)d_in[6];
    const float* Ug = (const float*)d_in[7];
    const float* Wg = (const float*)d_in[8];
    const float* bi = (const float*)d_in[9];
    const float* bf = (const float*)d_in[10];
    const float* bo = (const float*)d_in[11];
    const float* bg = (const float*)d_in[12];
    float* out = (float*)d_out;

    dim3 g1(EE / 128, (BB * SS) / 64);   // (32, 256)
    xproj_kernel<<<g1, 256>>>(X, Ui, Uf, Uo, Ug, bi, bf, bo, bg);

    cudaFuncSetAttribute(lstm_rec_mma,
                         cudaFuncAttributeMaxDynamicSharedMemorySize, REC_SMEM_BYTES);
    lstm_rec_mma<<<NBLK, 256, REC_SMEM_BYTES>>>(Wi, Wf, Wo, Wg, out);
}

// round 8
// speedup vs baseline: 1.6772x; 1.3476x over previous
#include <cuda_runtime.h>
#include <cuda_bf16.h>
#include <math.h>
#include <stdint.h>

// Problem constants
#define BB   32
#define SS   512
#define DD   1024
#define EE   4096          // 4*D
#define NBLK 128           // recurrence CTAs (all co-resident, 1/SM)

typedef unsigned long long u64;

// ---------- scratch (static __device__: no runtime allocation) ----------
__device__ __align__(16) float g_xp[(size_t)SS * BB * EE];       // x_proj [s][b][e]
__device__ __align__(16) __nv_bfloat16 g_Xhi[(size_t)BB * SS * DD];
__device__ __align__(16) __nv_bfloat16 g_Xlo[(size_t)BB * SS * DD];
__device__ __align__(16) __nv_bfloat16 g_Uthi[(size_t)EE * DD];  // U^T hi [e][k]
__device__ __align__(16) __nv_bfloat16 g_Utlo[(size_t)EE * DD];  // U^T lo [e][k]
__device__ __align__(16) __nv_bfloat16 g_hHi[BB * DD];           // h hi, [b][d]
__device__ __align__(16) __nv_bfloat16 g_hLo[BB * DD];           // h lo, [b][d]
__device__ u64 g_bar;                                            // init barrier (monotonic)
__device__ u64 g_leafArr[8][16];                                 // 128B-padded leaf counters
__device__ u64 g_leafRel[8][16];                                 // 128B-padded release counters
__device__ u64 g_rootArr;

__device__ __forceinline__ uint32_t smem_u32(const void* p) {
    uint32_t a;
    asm("{ .reg .u64 t; cvta.to.shared.u64 t, %1; cvt.u32.u64 %0, t; }" : "=r"(a) : "l"(p));
    return a;
}

__device__ __forceinline__ float sigf(float x) {
    float e = __expf(-x);
    float y; asm("rcp.approx.f32 %0, %1;" : "=f"(y) : "f"(1.0f + e));
    return y;
}

__device__ __forceinline__ uint32_t pack_bf2(float a, float b) {
    __nv_bfloat16 h0 = __float2bfloat16(a), h1 = __float2bfloat16(b);
    uint16_t u0, u1;
    memcpy(&u0, &h0, 2); memcpy(&u1, &h1, 2);
    return (uint32_t)u0 | ((uint32_t)u1 << 16);
}

#define LDMATRIX_X4(a0, a1, a2, a3, addr) \
    asm volatile("ldmatrix.sync.aligned.m8n8.x4.shared.b16 {%0,%1,%2,%3}, [%4];" \
                 : "=r"(a0), "=r"(a1), "=r"(a2), "=r"(a3) : "r"(addr))

#define MMA_BF16(c, a0, a1, a2, a3, b0, b1) \
    asm volatile("mma.sync.aligned.m16n8k16.row.col.f32.bf16.bf16.f32 " \
                 "{%0,%1,%2,%3}, {%4,%5,%6,%7}, {%8,%9}, {%0,%1,%2,%3};" \
                 : "+f"((c)[0]), "+f"((c)[1]), "+f"((c)[2]), "+f"((c)[3]) \
                 : "r"(a0), "r"(a1), "r"(a2), "r"(a3), "r"(b0), "r"(b1))

// =====================================================================
// Prep 1: split X (fp32 [b][s][k]) -> bf16 hi/lo, same layout (m=b*512+s rows)
// =====================================================================
__global__ void __launch_bounds__(256) splitX_kernel(const float* __restrict__ X)
{
    size_t i = ((size_t)blockIdx.x * 256 + threadIdx.x) * 4;
    float4 v = *(const float4*)(X + i);
    __nv_bfloat16 h0 = __float2bfloat16(v.x), h1 = __float2bfloat16(v.y);
    __nv_bfloat16 h2 = __float2bfloat16(v.z), h3 = __float2bfloat16(v.w);
    __nv_bfloat162 a01, a23, l01, l23;
    a01.x = h0; a01.y = h1; a23.x = h2; a23.y = h3;
    l01.x = __float2bfloat16(v.x - __bfloat162float(h0));
    l01.y = __float2bfloat16(v.y - __bfloat162float(h1));
    l23.x = __float2bfloat16(v.z - __bfloat162float(h2));
    l23.y = __float2bfloat16(v.w - __bfloat162float(h3));
    *(__nv_bfloat162*)(g_Xhi + i)     = a01;
    *(__nv_bfloat162*)(g_Xhi + i + 2) = a23;
    *(__nv_bfloat162*)(g_Xlo + i)     = l01;
    *(__nv_bfloat162*)(g_Xlo + i + 2) = l23;
}

// =====================================================================
// Prep 2: transpose + split U: g_Ut[e=gate*1024+col][k] = Ugate[k][col]
// grid (32, 32, 4), 256 threads, 32x32 tiles via smem
// =====================================================================
__global__ void __launch_bounds__(256) transU_kernel(
    const float* __restrict__ Ui, const float* __restrict__ Uf,
    const float* __restrict__ Uo, const float* __restrict__ Ug)
{
    __shared__ float t[32][33];
    const int gate = blockIdx.z;
    const float* U = (gate == 0) ? Ui : (gate == 1) ? Uf : (gate == 2) ? Uo : Ug;
    const int col0 = blockIdx.x * 32;
    const int k0   = blockIdx.y * 32;
    const int tx = threadIdx.x & 31, ty = threadIdx.x >> 5;

    #pragma unroll
    for (int rr = 0; rr < 4; rr++)
        t[ty + rr * 8][tx] = U[(size_t)(k0 + ty + rr * 8) * 1024 + col0 + tx];
    __syncthreads();
    #pragma unroll
    for (int rr = 0; rr < 4; rr++) {
        int c = ty + rr * 8;
        float v = t[tx][c];
        __nv_bfloat16 hi = __float2bfloat16(v);
        size_t dst = (size_t)(gate * 1024 + col0 + c) * 1024 + k0 + tx;
        g_Uthi[dst] = hi;
        g_Utlo[dst] = __float2bfloat16(v - __bfloat162float(hi));
    }
}

// =====================================================================
// Kernel 1: x_proj via HMMA bf16x3. C[16384][4096] = X@Ucat + b.
// CTA tile 128m x 64n, 8 warps (warp = 32x32), K-chunk 64, 16 chunks.
// SMEM: Ahi[128][72] Alo Bhi[64][72] Blo = 55296 B (dynamic)
// =====================================================================
#define XJ_SMEM 55296

__global__ void __launch_bounds__(256) xproj_mma(
    const float* __restrict__ bi, const float* __restrict__ bf_,
    const float* __restrict__ bo, const float* __restrict__ bg)
{
    extern __shared__ __nv_bfloat16 xsm[];
    __nv_bfloat16* Ahi = xsm;                 // [128][72]
    __nv_bfloat16* Alo = Ahi + 128 * 72;
    __nv_bfloat16* Bhi = Alo + 128 * 72;      // [64][72]
    __nv_bfloat16* Blo = Bhi + 64 * 72;

    const int tid  = threadIdx.x;
    const int wid  = tid >> 5;
    const int lane = tid & 31;
    const int n0   = blockIdx.x * 64;
    const int m0   = blockIdx.y * 128;
    const int gate = n0 >> 10;
    const float* bp = (gate == 0) ? bi : (gate == 1) ? bf_ : (gate == 2) ? bo : bg;

    const int mi2 = wid & 3;      // M 32-block
    const int nh2 = wid >> 2;     // N 32-block

    const uint32_t AhiU = smem_u32(Ahi), AloU = smem_u32(Alo);
    const uint32_t BhiU = smem_u32(Bhi), BloU = smem_u32(Blo);

    float c[2][4][4];
    #pragma unroll
    for (int mi = 0; mi < 2; mi++)
        #pragma unroll
        for (int nb = 0; nb < 4; nb++)
            #pragma unroll
            for (int q = 0; q < 4; q++) c[mi][nb][q] = 0.0f;

    for (int kc = 0; kc < 1024; kc += 64) {
        __syncthreads();
        // A: 128 rows x 8 u4 (hi + lo) = 2048 u4 -> 8 iters
        #pragma unroll
        for (int it = 0; it < 4; it++) {
            int idx = it * 256 + tid;
            int row = idx >> 3, k8 = idx & 7;
            size_t src = (size_t)(m0 + row) * 1024 + kc + k8 * 8;
            *(uint4*)&Ahi[row * 72 + k8 * 8] = *(const uint4*)&g_Xhi[src];
            *(uint4*)&Alo[row * 72 + k8 * 8] = *(const uint4*)&g_Xlo[src];
        }
        // B: 64 rows x 8 u4 (hi + lo) = 1024 u4 -> 4 iters
        #pragma unroll
        for (int it = 0; it < 2; it++) {
            int idx = it * 256 + tid;
            int row = idx >> 3, k8 = idx & 7;
            size_t src = (size_t)(n0 + row) * 1024 + kc + k8 * 8;
            *(uint4*)&Bhi[row * 72 + k8 * 8] = *(const uint4*)&g_Uthi[src];
            *(uint4*)&Blo[row * 72 + k8 * 8] = *(const uint4*)&g_Utlo[src];
        }
        __syncthreads();

        #pragma unroll
        for (int k16 = 0; k16 < 4; k16++) {
            const int kcol = k16 * 16;
            uint32_t ah[2][4], al[2][4], bh[2][4], bl[2][4];
            #pragma unroll
            for (int mi = 0; mi < 2; mi++) {
                uint32_t off = (uint32_t)(((mi2 * 32 + mi * 16 + (lane & 15)) * 72
                                           + kcol + (lane >> 4) * 8) * 2);
                LDMATRIX_X4(ah[mi][0], ah[mi][1], ah[mi][2], ah[mi][3], AhiU + off);
                LDMATRIX_X4(al[mi][0], al[mi][1], al[mi][2], al[mi][3], AloU + off);
            }
            #pragma unroll
            for (int nb2 = 0; nb2 < 2; nb2++) {
                int rowb = nh2 * 32 + nb2 * 16 + ((lane >> 4) << 3) + (lane & 7);
                int koff = kcol + ((lane >> 3) & 1) * 8;
                uint32_t off = (uint32_t)((rowb * 72 + koff) * 2);
                LDMATRIX_X4(bh[nb2][0], bh[nb2][1], bh[nb2][2], bh[nb2][3], BhiU + off);
                LDMATRIX_X4(bl[nb2][0], bl[nb2][1], bl[nb2][2], bl[nb2][3], BloU + off);
            }
            #pragma unroll
            for (int mi = 0; mi < 2; mi++)
                #pragma unroll
                for (int nb = 0; nb < 4; nb++) {
                    uint32_t b0 = bh[nb >> 1][(nb & 1) * 2];
                    uint32_t b1 = bh[nb >> 1][(nb & 1) * 2 + 1];
                    uint32_t c0 = bl[nb >> 1][(nb & 1) * 2];
                    uint32_t c1 = bl[nb >> 1][(nb & 1) * 2 + 1];
                    MMA_BF16(c[mi][nb], ah[mi][0], ah[mi][1], ah[mi][2], ah[mi][3], b0, b1);
                    MMA_BF16(c[mi][nb], al[mi][0], al[mi][1], al[mi][2], al[mi][3], b0, b1);
                    MMA_BF16(c[mi][nb], ah[mi][0], ah[mi][1], ah[mi][2], ah[mi][3], c0, c1);
                }
        }
    }

    // Epilogue: m -> (s = m&511, b = m>>9); write [s][b][e] + bias
    #pragma unroll
    for (int mi = 0; mi < 2; mi++)
        #pragma unroll
        for (int nb = 0; nb < 4; nb++) {
            int e_loc = nh2 * 32 + nb * 8 + (lane & 3) * 2;
            float bias0 = bp[(n0 & 1023) + e_loc];
            float bias1 = bp[(n0 & 1023) + e_loc + 1];
            #pragma unroll
            for (int h = 0; h < 2; h++) {
                int m = m0 + mi2 * 32 + mi * 16 + (lane >> 2) + h * 8;
                int s = m & 511, b = m >> 9;
                float2 v = {c[mi][nb][h * 2] + bias0, c[mi][nb][h * 2 + 1] + bias1};
                *(float2*)&g_xp[((size_t)s * BB + b) * EE + n0 + e_loc] = v;
            }
        }
}

// =====================================================================
// Kernel 2: HMMA recurrence. 128 persistent CTAs x 512 threads (16 warps).
// CTA owns 32 z-cols (gate*8 + dd). Warp (ks 0..7, nh 0..1): K-chunk 128.
//   z[32b][32j] = h[32][1024] @ Wslice[1024][32]  (bf16x3, f32 accum)
// Two-level grid barrier (8 leaf groups of 16 CTAs + root).
// SMEM: h hi/lo [32][1032]bf16 + red [8][32][32]f32 = 164864 B
// =====================================================================
#define H_STRIDE 1032
#define REC_SMEM_BYTES (2 * 32 * H_STRIDE * 2 + 8 * 32 * 32 * 4)

__global__ void __launch_bounds__(512, 1) lstm_rec_mma(
    const float* __restrict__ Wi, const float* __restrict__ Wf,
    const float* __restrict__ Wo, const float* __restrict__ Wg,
    float* __restrict__ out)
{
    extern __shared__ char sm[];
    __nv_bfloat16* sHi = (__nv_bfloat16*)sm;                   // [32][1032]
    __nv_bfloat16* sLo = sHi + 32 * H_STRIDE;
    float* red = (float*)(sm + 2 * 32 * H_STRIDE * 2);         // [8 ks][32 j][32 b]

    const int tid  = threadIdx.x;
    const int wid  = tid >> 5;
    const int lane = tid & 31;
    const int d0   = blockIdx.x * 8;
    const int grp  = blockIdx.x >> 4;

    const int ks = wid >> 1;          // K-chunk 0..7 (128 wide)
    const int nh = wid & 1;           // N-half
    const int kbase = ks << 7;
    const int lt2 = tid & 63;

    // ---- W fragments resident in registers ----
    uint32_t BHi[8][2][2], BLo[8][2][2];
    {
        const float* Wm[4] = {Wi, Wf, Wo, Wg};
        #pragma unroll
        for (int k16 = 0; k16 < 8; k16++)
            #pragma unroll
            for (int ni = 0; ni < 2; ni++)
                #pragma unroll
                for (int r = 0; r < 2; r++) {
                    int j = nh * 16 + ni * 8 + (lane >> 2);
                    int k0 = kbase + k16 * 16 + (lane & 3) * 2 + r * 8;
                    const float* wp = Wm[j >> 3] + (size_t)k0 * 1024 + d0 + (j & 7);
                    float w0 = __ldg(wp), w1 = __ldg(wp + 1024);
                    float h0 = __bfloat162float(__float2bfloat16(w0));
                    float h1 = __bfloat162float(__float2bfloat16(w1));
                    BHi[k16][ni][r] = pack_bf2(w0, w1);
                    BLo[k16][ni][r] = pack_bf2(w0 - h0, w1 - h1);
                }
    }

    // ---- zero h slice (first 256 threads: 32 b x 8 d) ----
    const int gb  = tid & 31;
    const int gdl = (tid >> 5) & 7;
    if (tid < 256) {
        g_hHi[gb * DD + d0 + gdl] = __float2bfloat16(0.0f);
        g_hLo[gb * DD + d0 + gdl] = __float2bfloat16(0.0f);
    }
    float c_reg = 0.0f;

    __threadfence();
    __syncthreads();

    // ---- read barrier epoch bases, then initial full grid barrier ----
    u64 leafBase = 0, rootBase = 0, relBase = 0;
    if (tid == 0) {
        leafBase = *((volatile u64*)&g_leafArr[grp][0]);
        rootBase = *((volatile u64*)&g_rootArr);
        relBase  = *((volatile u64*)&g_leafRel[grp][0]);
        u64 old = atomicAdd(&g_bar, 1ULL);
        u64 bs  = old - (old & (u64)(NBLK - 1));
        u64 tgt = bs + NBLK;
        while (*((volatile u64*)&g_bar) < tgt) { }
        __threadfence();
    }
    __syncthreads();

    const uint32_t sHi_u = smem_u32(sHi);
    const uint32_t sLo_u = smem_u32(sLo);

    for (int s = 0; s < SS; s++) {
        // xp prefetch (first 256 threads)
        float xp0, xp1, xp2, xp3;
        if (tid < 256) {
            const float* xpp = g_xp + ((size_t)s * BB + gb) * EE + d0 + gdl;
            xp0 = __ldg(xpp);
            xp1 = __ldg(xpp + 1024);
            xp2 = __ldg(xpp + 2048);
            xp3 = __ldg(xpp + 3072);
        }

        // ---- fill: warp-pair ks stages its 128-wide K-chunk (hi+lo) ----
        // 1024 u4 over 64 threads = 16 iters
        #pragma unroll 4
        for (int it = 0; it < 16; it++) {
            int idx = it * 64 + lt2;
            int arr = idx >> 9, rem = idx & 511;
            int b = rem >> 4, k8 = rem & 15;
            const __nv_bfloat16* src =
                (arr ? g_hLo : g_hHi) + b * DD + kbase + k8 * 8;
            uint4 v = __ldcg((const uint4*)src);
            __nv_bfloat16* dst = (arr ? sLo : sHi) + b * H_STRIDE + kbase + k8 * 8;
            *(uint4*)dst = v;
        }
        asm volatile("bar.sync %0, 64;" :: "r"(1 + ks) : "memory");

        // ---- MMA: 3 passes into one f32 acc ----
        float c[2][2][4];
        #pragma unroll
        for (int mi = 0; mi < 2; mi++)
            #pragma unroll
            for (int ni = 0; ni < 2; ni++)
                #pragma unroll
                for (int q = 0; q < 4; q++) c[mi][ni][q] = 0.0f;

        #pragma unroll
        for (int k16 = 0; k16 < 8; k16++) {
            const int kcol = kbase + k16 * 16;
            #pragma unroll
            for (int mi = 0; mi < 2; mi++) {
                uint32_t off = (uint32_t)(((mi * 16 + (lane & 15)) * H_STRIDE
                                           + kcol + (lane >> 4) * 8) * 2);
                uint32_t a0, a1, a2, a3, l0, l1, l2, l3;
                LDMATRIX_X4(a0, a1, a2, a3, sHi_u + off);
                LDMATRIX_X4(l0, l1, l2, l3, sLo_u + off);
                #pragma unroll
                for (int ni = 0; ni < 2; ni++) {
                    uint32_t b0 = BHi[k16][ni][0], b1 = BHi[k16][ni][1];
                    uint32_t c0 = BLo[k16][ni][0], c1 = BLo[k16][ni][1];
                    MMA_BF16(c[mi][ni], a0, a1, a2, a3, b0, b1);
                    MMA_BF16(c[mi][ni], l0, l1, l2, l3, b0, b1);
                    MMA_BF16(c[mi][ni], a0, a1, a2, a3, c0, c1);
                }
            }
        }

        // ---- store partials: red[ks][j][b] ----
        {
            float* rb = red + ks * 1024;
            #pragma unroll
            for (int mi = 0; mi < 2; mi++)
                #pragma unroll
                for (int ni = 0; ni < 2; ni++) {
                    int row0 = mi * 16 + (lane >> 2);
                    int col0 = nh * 16 + ni * 8 + (lane & 3) * 2;
                    rb[col0 * 32 + row0]           = c[mi][ni][0];
                    rb[(col0 + 1) * 32 + row0]     = c[mi][ni][1];
                    rb[col0 * 32 + row0 + 8]       = c[mi][ni][2];
                    rb[(col0 + 1) * 32 + row0 + 8] = c[mi][ni][3];
                }
        }
        __syncthreads();

        // ---- gates (first 256 threads) ----
        if (tid < 256) {
            float z0 = xp0, z1 = xp1, z2 = xp2, z3 = xp3;
            #pragma unroll
            for (int kk = 0; kk < 8; kk++) {
                const float* rb = red + kk * 1024;
                z0 += rb[(0 * 8 + gdl) * 32 + gb];
                z1 += rb[(1 * 8 + gdl) * 32 + gb];
                z2 += rb[(2 * 8 + gdl) * 32 + gb];
                z3 += rb[(3 * 8 + gdl) * 32 + gb];
            }
            float it = sigf(z0), ft = sigf(z1), ot = sigf(z2);
            float gt = tanhf(z3);
            float ct = sigf(ft * c_reg + it * gt);   // nonstandard cell (matches ref)
            float ht = tanhf(ct) * ot;
            c_reg = ct;
            out[((size_t)gb * SS + s) * DD + d0 + gdl] = ht;
            __nv_bfloat16 hh = __float2bfloat16(ht);
            __nv_bfloat16 hl = __float2bfloat16(ht - __bfloat162float(hh));
            g_hHi[gb * DD + d0 + gdl] = hh;
            g_hLo[gb * DD + d0 + gdl] = hl;
        }

        // ---- two-level grid barrier ----
        __threadfence();
        __syncthreads();
        if (tid == 0) {
            u64 a = atomicAdd(&g_leafArr[grp][0], 1ULL);
            if (a == leafBase + (u64)s * 16 + 15) {          // last in group
                u64 r = atomicAdd(&g_rootArr, 1ULL);
                if (r == rootBase + (u64)s * 8 + 7) {        // last overall
                    #pragma unroll
                    for (int g2 = 0; g2 < 8; g2++)
                        atomicAdd(&g_leafRel[g2][0], 1ULL);
                }
            }
            u64 want = relBase + (u64)s + 1;
            while (*((volatile u64*)&g_leafRel[grp][0]) < want) { }
            __threadfence();
        }
        __syncthreads();
    }
}

// =====================================================================
// Input order: 0:seq, 1:Ui, 2:Wi, 3:Uf, 4:Wf, 5:Uo, 6:Wo, 7:Ug, 8:Wg,
//              9:bi, 10:bf, 11:bo, 12:bg
// =====================================================================
extern "C" void kernel_launch(void* const* d_in, const int* in_sizes, int n_in,
                              void* d_out, int out_size)
{
    const float* X  = (const float*)d_in[0];
    const float* Ui = (const float*)d_in[1];
    const float* Wi = (const float*)d_in[2];
    const float* Uf = (const float*)d_in[3];
    const float* Wf = (const float*)d_in[4];
    const float* Uo = (const float*)d_in[5];
    const float* Wo = (const float*)d_in[6];
    const float* Ug = (const float*)d_in[7];
    const float* Wg = (const float*)d_in[8];
    const float* bi = (const float*)d_in[9];
    const float* bf = (const float*)d_in[10];
    const float* bo = (const float*)d_in[11];
    const float* bg = (const float*)d_in[12];
    float* out = (float*)d_out;

    // Prep: split X, transpose+split U
    splitX_kernel<<<(BB * SS * DD) / (256 * 4), 256>>>(X);
    dim3 gt(32, 32, 4);
    transU_kernel<<<gt, 256>>>(Ui, Uf, Uo, Ug);

    // x_proj GEMM (HMMA bf16x3)
    cudaFuncSetAttribute(xproj_mma,
                         cudaFuncAttributeMaxDynamicSharedMemorySize, XJ_SMEM);
    dim3 g1(EE / 64, (BB * SS) / 128);   // (64, 128)
    xproj_mma<<<g1, 256, XJ_SMEM>>>(bi, bf, bo, bg);

    // Recurrence (HMMA, persistent, two-level barrier)
    cudaFuncSetAttribute(lstm_rec_mma,
                         cudaFuncAttributeMaxDynamicSharedMemorySize, REC_SMEM_BYTES);
    lstm_rec_mma<<<NBLK, 512, REC_SMEM_BYTES>>>(Wi, Wf, Wo, Wg, out);
}

// round 11
// speedup vs baseline: 1.9805x; 1.1808x over previous
#include <cuda_runtime.h>
#include <cuda_bf16.h>
#include <math.h>
#include <stdint.h>

// Problem constants
#define BB   32
#define SS   512
#define DD   1024
#define EE   4096          // 4*D
#define NBLK 128           // recurrence CTAs (all co-resident, 1/SM)

typedef unsigned long long u64;

// ---------- scratch (static __device__: no runtime allocation) ----------
__device__ __align__(16) float g_xp[(size_t)SS * BB * EE];       // x_proj [s][b][e]
__device__ __align__(16) __nv_bfloat16 g_Xhi[(size_t)BB * SS * DD];
__device__ __align__(16) __nv_bfloat16 g_Xlo[(size_t)BB * SS * DD];
__device__ __align__(16) __nv_bfloat16 g_Uthi[(size_t)EE * DD];  // U^T hi [e][k]
__device__ __align__(16) __nv_bfloat16 g_Utlo[(size_t)EE * DD];  // U^T lo [e][k]
__device__ __align__(16) __nv_bfloat16 g_hHi[2][BB * DD];        // h hi, [par][b][d]
__device__ __align__(16) __nv_bfloat16 g_hLo[2][BB * DD];        // h lo, [par][b][d]
__device__ u64 g_bar;                                            // init barrier (monotonic)
__device__ u64 g_flag[NBLK][16];                                 // per-CTA step flags, 128B pad

__device__ __forceinline__ uint32_t smem_u32(const void* p) {
    uint32_t a;
    asm("{ .reg .u64 t; cvta.to.shared.u64 t, %1; cvt.u32.u64 %0, t; }" : "=r"(a) : "l"(p));
    return a;
}

__device__ __forceinline__ float sigf(float x) {
    float e = __expf(-x);
    float y; asm("rcp.approx.f32 %0, %1;" : "=f"(y) : "f"(1.0f + e));
    return y;
}

__device__ __forceinline__ float tanhf_fast(float x) {
    float e = __expf(2.0f * x);
    return 1.0f - __fdividef(2.0f, e + 1.0f);   // exact limits at +/-inf
}

__device__ __forceinline__ uint32_t pack_bf2(float a, float b) {
    __nv_bfloat16 h0 = __float2bfloat16(a), h1 = __float2bfloat16(b);
    uint16_t u0, u1;
    memcpy(&u0, &h0, 2); memcpy(&u1, &h1, 2);
    return (uint32_t)u0 | ((uint32_t)u1 << 16);
}

#define LDMATRIX_X4(a0, a1, a2, a3, addr) \
    asm volatile("ldmatrix.sync.aligned.m8n8.x4.shared.b16 {%0,%1,%2,%3}, [%4];" \
                 : "=r"(a0), "=r"(a1), "=r"(a2), "=r"(a3) : "r"(addr))

#define MMA_BF16(c, a0, a1, a2, a3, b0, b1) \
    asm volatile("mma.sync.aligned.m16n8k16.row.col.f32.bf16.bf16.f32 " \
                 "{%0,%1,%2,%3}, {%4,%5,%6,%7}, {%8,%9}, {%0,%1,%2,%3};" \
                 : "+f"((c)[0]), "+f"((c)[1]), "+f"((c)[2]), "+f"((c)[3]) \
                 : "r"(a0), "r"(a1), "r"(a2), "r"(a3), "r"(b0), "r"(b1))

// =====================================================================
// Prep 1: split X (fp32 [b][s][k]) -> bf16 hi/lo, same layout
// =====================================================================
__global__ void __launch_bounds__(256) splitX_kernel(const float* __restrict__ X)
{
    size_t i = ((size_t)blockIdx.x * 256 + threadIdx.x) * 4;
    float4 v = *(const float4*)(X + i);
    __nv_bfloat16 h0 = __float2bfloat16(v.x), h1 = __float2bfloat16(v.y);
    __nv_bfloat16 h2 = __float2bfloat16(v.z), h3 = __float2bfloat16(v.w);
    __nv_bfloat162 a01, a23, l01, l23;
    a01.x = h0; a01.y = h1; a23.x = h2; a23.y = h3;
    l01.x = __float2bfloat16(v.x - __bfloat162float(h0));
    l01.y = __float2bfloat16(v.y - __bfloat162float(h1));
    l23.x = __float2bfloat16(v.z - __bfloat162float(h2));
    l23.y = __float2bfloat16(v.w - __bfloat162float(h3));
    *(__nv_bfloat162*)(g_Xhi + i)     = a01;
    *(__nv_bfloat162*)(g_Xhi + i + 2) = a23;
    *(__nv_bfloat162*)(g_Xlo + i)     = l01;
    *(__nv_bfloat162*)(g_Xlo + i + 2) = l23;
}

// =====================================================================
// Prep 2: transpose + split U: g_Ut[e=gate*1024+col][k] = Ugate[k][col]
// =====================================================================
__global__ void __launch_bounds__(256) transU_kernel(
    const float* __restrict__ Ui, const float* __restrict__ Uf,
    const float* __restrict__ Uo, const float* __restrict__ Ug)
{
    __shared__ float t[32][33];
    const int gate = blockIdx.z;
    const float* U = (gate == 0) ? Ui : (gate == 1) ? Uf : (gate == 2) ? Uo : Ug;
    const int col0 = blockIdx.x * 32;
    const int k0   = blockIdx.y * 32;
    const int tx = threadIdx.x & 31, ty = threadIdx.x >> 5;

    #pragma unroll
    for (int rr = 0; rr < 4; rr++)
        t[ty + rr * 8][tx] = U[(size_t)(k0 + ty + rr * 8) * 1024 + col0 + tx];
    __syncthreads();
    #pragma unroll
    for (int rr = 0; rr < 4; rr++) {
        int c = ty + rr * 8;
        float v = t[tx][c];
        __nv_bfloat16 hi = __float2bfloat16(v);
        size_t dst = (size_t)(gate * 1024 + col0 + c) * 1024 + k0 + tx;
        g_Uthi[dst] = hi;
        g_Utlo[dst] = __float2bfloat16(v - __bfloat162float(hi));
    }
}

// =====================================================================
// Kernel 1: x_proj via HMMA bf16x3. CTA tile 128m x 64n, 8 warps.
// =====================================================================
#define XJ_SMEM 55296

__global__ void __launch_bounds__(256) xproj_mma(
    const float* __restrict__ bi, const float* __restrict__ bf_,
    const float* __restrict__ bo, const float* __restrict__ bg)
{
    extern __shared__ __nv_bfloat16 xsm[];
    __nv_bfloat16* Ahi = xsm;                 // [128][72]
    __nv_bfloat16* Alo = Ahi + 128 * 72;
    __nv_bfloat16* Bhi = Alo + 128 * 72;      // [64][72]
    __nv_bfloat16* Blo = Bhi + 64 * 72;

    const int tid  = threadIdx.x;
    const int wid  = tid >> 5;
    const int lane = tid & 31;
    const int n0   = blockIdx.x * 64;
    const int m0   = blockIdx.y * 128;
    const int gate = n0 >> 10;
    const float* bp = (gate == 0) ? bi : (gate == 1) ? bf_ : (gate == 2) ? bo : bg;

    const int mi2 = wid & 3;
    const int nh2 = wid >> 2;

    const uint32_t AhiU = smem_u32(Ahi), AloU = smem_u32(Alo);
    const uint32_t BhiU = smem_u32(Bhi), BloU = smem_u32(Blo);

    float c[2][4][4];
    #pragma unroll
    for (int mi = 0; mi < 2; mi++)
        #pragma unroll
        for (int nb = 0; nb < 4; nb++)
            #pragma unroll
            for (int q = 0; q < 4; q++) c[mi][nb][q] = 0.0f;

    for (int kc = 0; kc < 1024; kc += 64) {
        __syncthreads();
        #pragma unroll
        for (int it = 0; it < 4; it++) {
            int idx = it * 256 + tid;
            int row = idx >> 3, k8 = idx & 7;
            size_t src = (size_t)(m0 + row) * 1024 + kc + k8 * 8;
            *(uint4*)&Ahi[row * 72 + k8 * 8] = *(const uint4*)&g_Xhi[src];
            *(uint4*)&Alo[row * 72 + k8 * 8] = *(const uint4*)&g_Xlo[src];
        }
        #pragma unroll
        for (int it = 0; it < 2; it++) {
            int idx = it * 256 + tid;
            int row = idx >> 3, k8 = idx & 7;
            size_t src = (size_t)(n0 + row) * 1024 + kc + k8 * 8;
            *(uint4*)&Bhi[row * 72 + k8 * 8] = *(const uint4*)&g_Uthi[src];
            *(uint4*)&Blo[row * 72 + k8 * 8] = *(const uint4*)&g_Utlo[src];
        }
        __syncthreads();

        #pragma unroll
        for (int k16 = 0; k16 < 4; k16++) {
            const int kcol = k16 * 16;
            uint32_t ah[2][4], al[2][4], bh[2][4], bl[2][4];
            #pragma unroll
            for (int mi = 0; mi < 2; mi++) {
                uint32_t off = (uint32_t)(((mi2 * 32 + mi * 16 + (lane & 15)) * 72
                                           + kcol + (lane >> 4) * 8) * 2);
                LDMATRIX_X4(ah[mi][0], ah[mi][1], ah[mi][2], ah[mi][3], AhiU + off);
                LDMATRIX_X4(al[mi][0], al[mi][1], al[mi][2], al[mi][3], AloU + off);
            }
            #pragma unroll
            for (int nb2 = 0; nb2 < 2; nb2++) {
                int rowb = nh2 * 32 + nb2 * 16 + ((lane >> 4) << 3) + (lane & 7);
                int koff = kcol + ((lane >> 3) & 1) * 8;
                uint32_t off = (uint32_t)((rowb * 72 + koff) * 2);
                LDMATRIX_X4(bh[nb2][0], bh[nb2][1], bh[nb2][2], bh[nb2][3], BhiU + off);
                LDMATRIX_X4(bl[nb2][0], bl[nb2][1], bl[nb2][2], bl[nb2][3], BloU + off);
            }
            #pragma unroll
            for (int mi = 0; mi < 2; mi++)
                #pragma unroll
                for (int nb = 0; nb < 4; nb++) {
                    uint32_t b0 = bh[nb >> 1][(nb & 1) * 2];
                    uint32_t b1 = bh[nb >> 1][(nb & 1) * 2 + 1];
                    uint32_t c0 = bl[nb >> 1][(nb & 1) * 2];
                    uint32_t c1 = bl[nb >> 1][(nb & 1) * 2 + 1];
                    MMA_BF16(c[mi][nb], ah[mi][0], ah[mi][1], ah[mi][2], ah[mi][3], b0, b1);
                    MMA_BF16(c[mi][nb], al[mi][0], al[mi][1], al[mi][2], al[mi][3], b0, b1);
                    MMA_BF16(c[mi][nb], ah[mi][0], ah[mi][1], ah[mi][2], ah[mi][3], c0, c1);
                }
        }
    }

    #pragma unroll
    for (int mi = 0; mi < 2; mi++)
        #pragma unroll
        for (int nb = 0; nb < 4; nb++) {
            int e_loc = nh2 * 32 + nb * 8 + (lane & 3) * 2;
            float bias0 = bp[(n0 & 1023) + e_loc];
            float bias1 = bp[(n0 & 1023) + e_loc + 1];
            #pragma unroll
            for (int h = 0; h < 2; h++) {
                int m = m0 + mi2 * 32 + mi * 16 + (lane >> 2) + h * 8;
                int s = m & 511, b = m >> 9;
                float2 v = {c[mi][nb][h * 2] + bias0, c[mi][nb][h * 2 + 1] + bias1};
                *(float2*)&g_xp[((size_t)s * BB + b) * EE + n0 + e_loc] = v;
            }
        }
}

// =====================================================================
// Kernel 2: HMMA recurrence with flag-based fine-grained sync.
// 128 persistent CTAs x 512 threads. CTA owns 32 z-cols (4 gates x 8 d).
// Warp-pair ks consumes K-chunk [128ks,128ks+128) = producers 16ks..16ks+15;
// polling thread lt2 polls EXACTLY the producer whose 8-d slice it loads.
// h double-buffered by step parity; flag[cta] = steps completed (release).
// =====================================================================
#define H_STRIDE 1032
#define REC_SMEM_BYTES (2 * 32 * H_STRIDE * 2 + 8 * 32 * 32 * 4)

__global__ void __launch_bounds__(512, 1) lstm_rec_mma(
    const float* __restrict__ Wi, const float* __restrict__ Wf,
    const float* __restrict__ Wo, const float* __restrict__ Wg,
    float* __restrict__ out)
{
    extern __shared__ char sm[];
    __nv_bfloat16* sHi = (__nv_bfloat16*)sm;                   // [32][1032]
    __nv_bfloat16* sLo = sHi + 32 * H_STRIDE;
    float* red = (float*)(sm + 2 * 32 * H_STRIDE * 2);         // [8 ks][32 j][32 b]

    const int tid  = threadIdx.x;
    const int wid  = tid >> 5;
    const int lane = tid & 31;
    const int d0   = blockIdx.x * 8;

    const int ks = wid >> 1;          // K-chunk 0..7 (128 wide)
    const int nh = wid & 1;           // N-half
    const int kbase = ks << 7;
    const int lt2 = tid & 63;

    // Flag this thread polls: the producer of the d-slice it loads in fill
    const u64* pollp = &g_flag[16 * ks + (lt2 & 15)][0];

    // ---- W fragments resident in registers ----
    uint32_t BHi[8][2][2], BLo[8][2][2];
    {
        const float* Wm[4] = {Wi, Wf, Wo, Wg};
        #pragma unroll
        for (int k16 = 0; k16 < 8; k16++)
            #pragma unroll
            for (int ni = 0; ni < 2; ni++)
                #pragma unroll
                for (int r = 0; r < 2; r++) {
                    int j = nh * 16 + ni * 8 + (lane >> 2);
                    int k0 = kbase + k16 * 16 + (lane & 3) * 2 + r * 8;
                    const float* wp = Wm[j >> 3] + (size_t)k0 * 1024 + d0 + (j & 7);
                    float w0 = __ldg(wp), w1 = __ldg(wp + 1024);
                    float h0 = __bfloat162float(__float2bfloat16(w0));
                    float h1 = __bfloat162float(__float2bfloat16(w1));
                    BHi[k16][ni][r] = pack_bf2(w0, w1);
                    BLo[k16][ni][r] = pack_bf2(w0 - h0, w1 - h1);
                }
    }

    // ---- init: zero h_{-1} (buffer 1) slice, reset own flag ----
    const int gb  = tid & 31;
    const int gdl = (tid >> 5) & 7;
    if (tid < 256) {
        g_hHi[1][gb * DD + d0 + gdl] = __float2bfloat16(0.0f);
        g_hLo[1][gb * DD + d0 + gdl] = __float2bfloat16(0.0f);
    }
    if (tid == 0) g_flag[blockIdx.x][0] = 0ULL;
    float c_reg = 0.0f;

    __threadfence();
    __syncthreads();

    // ---- initial full grid barrier (monotonic counter, epoch-derived) ----
    if (tid == 0) {
        u64 old = atomicAdd(&g_bar, 1ULL);
        u64 bs  = old - (old & (u64)(NBLK - 1));
        u64 tgt = bs + NBLK;
        while (*((volatile u64*)&g_bar) < tgt) { }
        __threadfence();
    }
    __syncthreads();

    const uint32_t sHi_u = smem_u32(sHi);
    const uint32_t sLo_u = smem_u32(sLo);

    for (int s = 0; s < SS; s++) {
        const int rpar = (s + 1) & 1;    // buffer holding h_{s-1}
        const int wpar = s & 1;          // buffer for h_s

        // xp prefetch (first 256 threads)
        float xp0, xp1, xp2, xp3;
        if (tid < 256) {
            const float* xpp = g_xp + ((size_t)s * BB + gb) * EE + d0 + gdl;
            xp0 = __ldg(xpp);
            xp1 = __ldg(xpp + 1024);
            xp2 = __ldg(xpp + 2048);
            xp3 = __ldg(xpp + 3072);
        }

        // ---- wait for my producer (acquire), then stage its data ----
        {
            u64 v;
            do {
                asm volatile("ld.acquire.gpu.global.u64 %0, [%1];"
                             : "=l"(v) : "l"(pollp));
            } while (v < (u64)s);
        }
        const __nv_bfloat16* srcHi = g_hHi[rpar];
        const __nv_bfloat16* srcLo = g_hLo[rpar];
        #pragma unroll 4
        for (int it = 0; it < 16; it++) {
            int idx = it * 64 + lt2;
            int arr = idx >> 9, rem = idx & 511;
            int b = rem >> 4, k8 = rem & 15;
            const __nv_bfloat16* src = (arr ? srcLo : srcHi) + b * DD + kbase + k8 * 8;
            uint4 v = __ldcg((const uint4*)src);
            __nv_bfloat16* dst = (arr ? sLo : sHi) + b * H_STRIDE + kbase + k8 * 8;
            *(uint4*)dst = v;
        }
        asm volatile("bar.sync %0, 64;" :: "r"(1 + ks) : "memory");

        // ---- MMA: bf16x3, one f32 acc ----
        float c[2][2][4];
        #pragma unroll
        for (int mi = 0; mi < 2; mi++)
            #pragma unroll
            for (int ni = 0; ni < 2; ni++)
                #pragma unroll
                for (int q = 0; q < 4; q++) c[mi][ni][q] = 0.0f;

        #pragma unroll
        for (int k16 = 0; k16 < 8; k16++) {
            const int kcol = kbase + k16 * 16;
            #pragma unroll
            for (int mi = 0; mi < 2; mi++) {
                uint32_t off = (uint32_t)(((mi * 16 + (lane & 15)) * H_STRIDE
                                           + kcol + (lane >> 4) * 8) * 2);
                uint32_t a0, a1, a2, a3, l0, l1, l2, l3;
                LDMATRIX_X4(a0, a1, a2, a3, sHi_u + off);
                LDMATRIX_X4(l0, l1, l2, l3, sLo_u + off);
                #pragma unroll
                for (int ni = 0; ni < 2; ni++) {
                    uint32_t b0 = BHi[k16][ni][0], b1 = BHi[k16][ni][1];
                    uint32_t c0 = BLo[k16][ni][0], c1 = BLo[k16][ni][1];
                    MMA_BF16(c[mi][ni], a0, a1, a2, a3, b0, b1);
                    MMA_BF16(c[mi][ni], l0, l1, l2, l3, b0, b1);
                    MMA_BF16(c[mi][ni], a0, a1, a2, a3, c0, c1);
                }
            }
        }

        // ---- store partials: red[ks][j][b] ----
        {
            float* rb = red + ks * 1024;
            #pragma unroll
            for (int mi = 0; mi < 2; mi++)
                #pragma unroll
                for (int ni = 0; ni < 2; ni++) {
                    int row0 = mi * 16 + (lane >> 2);
                    int col0 = nh * 16 + ni * 8 + (lane & 3) * 2;
                    rb[col0 * 32 + row0]           = c[mi][ni][0];
                    rb[(col0 + 1) * 32 + row0]     = c[mi][ni][1];
                    rb[col0 * 32 + row0 + 8]       = c[mi][ni][2];
                    rb[(col0 + 1) * 32 + row0 + 8] = c[mi][ni][3];
                }
        }
        __syncthreads();   // also joins the 8 partial-poll groups -> all 128 flags >= s seen

        // ---- gates (first 256 threads) ----
        if (tid < 256) {
            float z0 = xp0, z1 = xp1, z2 = xp2, z3 = xp3;
            #pragma unroll
            for (int kk = 0; kk < 8; kk++) {
                const float* rb = red + kk * 1024;
                z0 += rb[(0 * 8 + gdl) * 32 + gb];
                z1 += rb[(1 * 8 + gdl) * 32 + gb];
                z2 += rb[(2 * 8 + gdl) * 32 + gb];
                z3 += rb[(3 * 8 + gdl) * 32 + gb];
            }
            float it = sigf(z0), ft = sigf(z1), ot = sigf(z2);
            float gt = tanhf_fast(z3);
            float ct = sigf(ft * c_reg + it * gt);   // nonstandard cell (matches ref)
            float ht = tanhf_fast(ct) * ot;
            c_reg = ct;
            out[((size_t)gb * SS + s) * DD + d0 + gdl] = ht;
            __nv_bfloat16 hh = __float2bfloat16(ht);
            __nv_bfloat16 hl = __float2bfloat16(ht - __bfloat162float(hh));
            g_hHi[wpar][gb * DD + d0 + gdl] = hh;
            g_hLo[wpar][gb * DD + d0 + gdl] = hl;
        }

        // ---- publish: flag[cta] = s+1 (release) ----
        __syncthreads();
        if (tid == 0) {
            asm volatile("st.release.gpu.global.u64 [%0], %1;"
                         :: "l"(&g_flag[blockIdx.x][0]), "l"((u64)(s + 1)) : "memory");
        }
    }
}

// =====================================================================
// Input order: 0:seq, 1:Ui, 2:Wi, 3:Uf, 4:Wf, 5:Uo, 6:Wo, 7:Ug, 8:Wg,
//              9:bi, 10:bf, 11:bo, 12:bg
// =====================================================================
extern "C" void kernel_launch(void* const* d_in, const int* in_sizes, int n_in,
                              void* d_out, int out_size)
{
    const float* X  = (const float*)d_in[0];
    const float* Ui = (const float*)d_in[1];
    const float* Wi = (const float*)d_in[2];
    const float* Uf = (const float*)d_in[3];
    const float* Wf = (const float*)d_in[4];
    const float* Uo = (const float*)d_in[5];
    const float* Wo = (const float*)d_in[6];
    const float* Ug = (const float*)d_in[7];
    const float* Wg = (const float*)d_in[8];
    const float* bi = (const float*)d_in[9];
    const float* bf = (const float*)d_in[10];
    const float* bo = (const float*)d_in[11];
    const float* bg = (const float*)d_in[12];
    float* out = (float*)d_out;

    // Prep: split X, transpose+split U
    splitX_kernel<<<(BB * SS * DD) / (256 * 4), 256>>>(X);
    dim3 gt(32, 32, 4);
    transU_kernel<<<gt, 256>>>(Ui, Uf, Uo, Ug);

    // x_proj GEMM (HMMA bf16x3)
    cudaFuncSetAttribute(xproj_mma,
                         cudaFuncAttributeMaxDynamicSharedMemorySize, XJ_SMEM);
    dim3 g1(EE / 64, (BB * SS) / 128);   // (64, 128)
    xproj_mma<<<g1, 256, XJ_SMEM>>>(bi, bf, bo, bg);

    // Recurrence (HMMA, persistent, flag-based sync)
    cudaFuncSetAttribute(lstm_rec_mma,
                         cudaFuncAttributeMaxDynamicSharedMemorySize, REC_SMEM_BYTES);
    lstm_rec_mma<<<NBLK, 512, REC_SMEM_BYTES>>>(Wi, Wf, Wo, Wg, out);
}

// round 12
// speedup vs baseline: 1.9889x; 1.0043x over previous
#include <cuda_runtime.h>
#include <cuda_bf16.h>
#include <math.h>
#include <stdint.h>

// Problem constants
#define BB   32
#define SS   512
#define DD   1024
#define EE   4096          // 4*D
#define NBLK 128           // recurrence CTAs (all co-resident, 1/SM)

typedef unsigned long long u64;

// ---------- scratch (static __device__: no runtime allocation) ----------
__device__ __align__(16) float g_xp[(size_t)SS * BB * EE];       // x_proj [s][b][e]
__device__ __align__(16) __nv_bfloat16 g_Xhi[(size_t)BB * SS * DD];
__device__ __align__(16) __nv_bfloat16 g_Xlo[(size_t)BB * SS * DD];
__device__ __align__(16) __nv_bfloat16 g_Uthi[(size_t)EE * DD];  // U^T hi [e][k]
__device__ __align__(16) __nv_bfloat16 g_Utlo[(size_t)EE * DD];  // U^T lo [e][k]
__device__ __align__(16) __nv_bfloat16 g_hHi[2][BB * DD];        // h hi, [par][b][d]
__device__ __align__(16) __nv_bfloat16 g_hLo[2][BB * DD];        // h lo, [par][b][d]
__device__ u64 g_bar;                                            // init barrier (monotonic)
__device__ u64 g_flag[NBLK][16];                                 // per-CTA step flags, 128B pad

__device__ __forceinline__ uint32_t smem_u32(const void* p) {
    uint32_t a;
    asm("{ .reg .u64 t; cvta.to.shared.u64 t, %1; cvt.u32.u64 %0, t; }" : "=r"(a) : "l"(p));
    return a;
}

__device__ __forceinline__ float sigf(float x) {
    float e = __expf(-x);
    float y; asm("rcp.approx.f32 %0, %1;" : "=f"(y) : "f"(1.0f + e));
    return y;
}

__device__ __forceinline__ float tanhf_fast(float x) {
    float e = __expf(2.0f * x);
    return 1.0f - __fdividef(2.0f, e + 1.0f);   // exact limits at +/-inf
}

__device__ __forceinline__ uint32_t pack_bf2(float a, float b) {
    __nv_bfloat16 h0 = __float2bfloat16(a), h1 = __float2bfloat16(b);
    uint16_t u0, u1;
    memcpy(&u0, &h0, 2); memcpy(&u1, &h1, 2);
    return (uint32_t)u0 | ((uint32_t)u1 << 16);
}

#define LDMATRIX_X4(a0, a1, a2, a3, addr) \
    asm volatile("ldmatrix.sync.aligned.m8n8.x4.shared.b16 {%0,%1,%2,%3}, [%4];" \
                 : "=r"(a0), "=r"(a1), "=r"(a2), "=r"(a3) : "r"(addr))

#define MMA_BF16(c, a0, a1, a2, a3, b0, b1) \
    asm volatile("mma.sync.aligned.m16n8k16.row.col.f32.bf16.bf16.f32 " \
                 "{%0,%1,%2,%3}, {%4,%5,%6,%7}, {%8,%9}, {%0,%1,%2,%3};" \
                 : "+f"((c)[0]), "+f"((c)[1]), "+f"((c)[2]), "+f"((c)[3]) \
                 : "r"(a0), "r"(a1), "r"(a2), "r"(a3), "r"(b0), "r"(b1))

// =====================================================================
// Prep 1: split X (fp32 [b][s][k]) -> bf16 hi/lo, same layout
// =====================================================================
__global__ void __launch_bounds__(256) splitX_kernel(const float* __restrict__ X)
{
    size_t i = ((size_t)blockIdx.x * 256 + threadIdx.x) * 4;
    float4 v = *(const float4*)(X + i);
    __nv_bfloat16 h0 = __float2bfloat16(v.x), h1 = __float2bfloat16(v.y);
    __nv_bfloat16 h2 = __float2bfloat16(v.z), h3 = __float2bfloat16(v.w);
    __nv_bfloat162 a01, a23, l01, l23;
    a01.x = h0; a01.y = h1; a23.x = h2; a23.y = h3;
    l01.x = __float2bfloat16(v.x - __bfloat162float(h0));
    l01.y = __float2bfloat16(v.y - __bfloat162float(h1));
    l23.x = __float2bfloat16(v.z - __bfloat162float(h2));
    l23.y = __float2bfloat16(v.w - __bfloat162float(h3));
    *(__nv_bfloat162*)(g_Xhi + i)     = a01;
    *(__nv_bfloat162*)(g_Xhi + i + 2) = a23;
    *(__nv_bfloat162*)(g_Xlo + i)     = l01;
    *(__nv_bfloat162*)(g_Xlo + i + 2) = l23;
}

// =====================================================================
// Prep 2: transpose + split U: g_Ut[e=gate*1024+col][k] = Ugate[k][col]
// =====================================================================
__global__ void __launch_bounds__(256) transU_kernel(
    const float* __restrict__ Ui, const float* __restrict__ Uf,
    const float* __restrict__ Uo, const float* __restrict__ Ug)
{
    __shared__ float t[32][33];
    const int gate = blockIdx.z;
    const float* U = (gate == 0) ? Ui : (gate == 1) ? Uf : (gate == 2) ? Uo : Ug;
    const int col0 = blockIdx.x * 32;
    const int k0   = blockIdx.y * 32;
    const int tx = threadIdx.x & 31, ty = threadIdx.x >> 5;

    #pragma unroll
    for (int rr = 0; rr < 4; rr++)
        t[ty + rr * 8][tx] = U[(size_t)(k0 + ty + rr * 8) * 1024 + col0 + tx];
    __syncthreads();
    #pragma unroll
    for (int rr = 0; rr < 4; rr++) {
        int c = ty + rr * 8;
        float v = t[tx][c];
        __nv_bfloat16 hi = __float2bfloat16(v);
        size_t dst = (size_t)(gate * 1024 + col0 + c) * 1024 + k0 + tx;
        g_Uthi[dst] = hi;
        g_Utlo[dst] = __float2bfloat16(v - __bfloat162float(hi));
    }
}

// =====================================================================
// Kernel 1: x_proj via HMMA bf16x3. CTA tile 128m x 64n, 8 warps.
// =====================================================================
#define XJ_SMEM 55296

__global__ void __launch_bounds__(256) xproj_mma(
    const float* __restrict__ bi, const float* __restrict__ bf_,
    const float* __restrict__ bo, const float* __restrict__ bg)
{
    extern __shared__ __nv_bfloat16 xsm[];
    __nv_bfloat16* Ahi = xsm;                 // [128][72]
    __nv_bfloat16* Alo = Ahi + 128 * 72;
    __nv_bfloat16* Bhi = Alo + 128 * 72;      // [64][72]
    __nv_bfloat16* Blo = Bhi + 64 * 72;

    const int tid  = threadIdx.x;
    const int wid  = tid >> 5;
    const int lane = tid & 31;
    const int n0   = blockIdx.x * 64;
    const int m0   = blockIdx.y * 128;
    const int gate = n0 >> 10;
    const float* bp = (gate == 0) ? bi : (gate == 1) ? bf_ : (gate == 2) ? bo : bg;

    const int mi2 = wid & 3;
    const int nh2 = wid >> 2;

    const uint32_t AhiU = smem_u32(Ahi), AloU = smem_u32(Alo);
    const uint32_t BhiU = smem_u32(Bhi), BloU = smem_u32(Blo);

    float c[2][4][4];
    #pragma unroll
    for (int mi = 0; mi < 2; mi++)
        #pragma unroll
        for (int nb = 0; nb < 4; nb++)
            #pragma unroll
            for (int q = 0; q < 4; q++) c[mi][nb][q] = 0.0f;

    for (int kc = 0; kc < 1024; kc += 64) {
        __syncthreads();
        #pragma unroll
        for (int it = 0; it < 4; it++) {
            int idx = it * 256 + tid;
            int row = idx >> 3, k8 = idx & 7;
            size_t src = (size_t)(m0 + row) * 1024 + kc + k8 * 8;
            *(uint4*)&Ahi[row * 72 + k8 * 8] = *(const uint4*)&g_Xhi[src];
            *(uint4*)&Alo[row * 72 + k8 * 8] = *(const uint4*)&g_Xlo[src];
        }
        #pragma unroll
        for (int it = 0; it < 2; it++) {
            int idx = it * 256 + tid;
            int row = idx >> 3, k8 = idx & 7;
            size_t src = (size_t)(n0 + row) * 1024 + kc + k8 * 8;
            *(uint4*)&Bhi[row * 72 + k8 * 8] = *(const uint4*)&g_Uthi[src];
            *(uint4*)&Blo[row * 72 + k8 * 8] = *(const uint4*)&g_Utlo[src];
        }
        __syncthreads();

        #pragma unroll
        for (int k16 = 0; k16 < 4; k16++) {
            const int kcol = k16 * 16;
            uint32_t ah[2][4], al[2][4], bh[2][4], bl[2][4];
            #pragma unroll
            for (int mi = 0; mi < 2; mi++) {
                uint32_t off = (uint32_t)(((mi2 * 32 + mi * 16 + (lane & 15)) * 72
                                           + kcol + (lane >> 4) * 8) * 2);
                LDMATRIX_X4(ah[mi][0], ah[mi][1], ah[mi][2], ah[mi][3], AhiU + off);
                LDMATRIX_X4(al[mi][0], al[mi][1], al[mi][2], al[mi][3], AloU + off);
            }
            #pragma unroll
            for (int nb2 = 0; nb2 < 2; nb2++) {
                int rowb = nh2 * 32 + nb2 * 16 + ((lane >> 4) << 3) + (lane & 7);
                int koff = kcol + ((lane >> 3) & 1) * 8;
                uint32_t off = (uint32_t)((rowb * 72 + koff) * 2);
                LDMATRIX_X4(bh[nb2][0], bh[nb2][1], bh[nb2][2], bh[nb2][3], BhiU + off);
                LDMATRIX_X4(bl[nb2][0], bl[nb2][1], bl[nb2][2], bl[nb2][3], BloU + off);
            }
            #pragma unroll
            for (int mi = 0; mi < 2; mi++)
                #pragma unroll
                for (int nb = 0; nb < 4; nb++) {
                    uint32_t b0 = bh[nb >> 1][(nb & 1) * 2];
                    uint32_t b1 = bh[nb >> 1][(nb & 1) * 2 + 1];
                    uint32_t c0 = bl[nb >> 1][(nb & 1) * 2];
                    uint32_t c1 = bl[nb >> 1][(nb & 1) * 2 + 1];
                    MMA_BF16(c[mi][nb], ah[mi][0], ah[mi][1], ah[mi][2], ah[mi][3], b0, b1);
                    MMA_BF16(c[mi][nb], al[mi][0], al[mi][1], al[mi][2], al[mi][3], b0, b1);
                    MMA_BF16(c[mi][nb], ah[mi][0], ah[mi][1], ah[mi][2], ah[mi][3], c0, c1);
                }
        }
    }

    #pragma unroll
    for (int mi = 0; mi < 2; mi++)
        #pragma unroll
        for (int nb = 0; nb < 4; nb++) {
            int e_loc = nh2 * 32 + nb * 8 + (lane & 3) * 2;
            float bias0 = bp[(n0 & 1023) + e_loc];
            float bias1 = bp[(n0 & 1023) + e_loc + 1];
            #pragma unroll
            for (int h = 0; h < 2; h++) {
                int m = m0 + mi2 * 32 + mi * 16 + (lane >> 2) + h * 8;
                int s = m & 511, b = m >> 9;
                float2 v = {c[mi][nb][h * 2] + bias0, c[mi][nb][h * 2 + 1] + bias1};
                *(float2*)&g_xp[((size_t)s * BB + b) * EE + n0 + e_loc] = v;
            }
        }
}

// =====================================================================
// Kernel 2: HMMA recurrence, flag-sync, decoupled gates tail.
// 128 persistent CTAs x 512 threads. CTA owns 32 z-cols (4 gates x 8 d).
// Warp-pair ks consumes K-chunk [128ks,128ks+128) = producers 16ks..16ks+15.
// red double-buffered by parity: MMA warps (8-15) skip the gates barrier
// and start next step's poll+fill while warps 0-7 run the gates tail.
// WAR on red[par] at s+2 is transitively blocked by the flag protocol.
// =====================================================================
#define H_STRIDE 1032
#define REC_SMEM_BYTES (2 * 32 * H_STRIDE * 2 + 2 * 8 * 32 * 32 * 4)  // 197632

__global__ void __launch_bounds__(512, 1) lstm_rec_mma(
    const float* __restrict__ Wi, const float* __restrict__ Wf,
    const float* __restrict__ Wo, const float* __restrict__ Wg,
    float* __restrict__ out)
{
    extern __shared__ char sm[];
    __nv_bfloat16* sHi = (__nv_bfloat16*)sm;                   // [32][1032]
    __nv_bfloat16* sLo = sHi + 32 * H_STRIDE;
    float* red = (float*)(sm + 2 * 32 * H_STRIDE * 2);         // [2 par][8 ks][32 j][32 b]

    const int tid  = threadIdx.x;
    const int wid  = tid >> 5;
    const int lane = tid & 31;
    const int d0   = blockIdx.x * 8;

    const int ks = wid >> 1;          // K-chunk 0..7 (128 wide)
    const int nh = wid & 1;           // N-half
    const int kbase = ks << 7;
    const int lt2 = tid & 63;

    // Flag this thread polls: the producer of the d-slice it loads in fill
    const u64* pollp = &g_flag[16 * ks + (lt2 & 15)][0];

    // ---- W fragments resident in registers ----
    uint32_t BHi[8][2][2], BLo[8][2][2];
    {
        const float* Wm[4] = {Wi, Wf, Wo, Wg};
        #pragma unroll
        for (int k16 = 0; k16 < 8; k16++)
            #pragma unroll
            for (int ni = 0; ni < 2; ni++)
                #pragma unroll
                for (int r = 0; r < 2; r++) {
                    int j = nh * 16 + ni * 8 + (lane >> 2);
                    int k0 = kbase + k16 * 16 + (lane & 3) * 2 + r * 8;
                    const float* wp = Wm[j >> 3] + (size_t)k0 * 1024 + d0 + (j & 7);
                    float w0 = __ldg(wp), w1 = __ldg(wp + 1024);
                    float h0 = __bfloat162float(__float2bfloat16(w0));
                    float h1 = __bfloat162float(__float2bfloat16(w1));
                    BHi[k16][ni][r] = pack_bf2(w0, w1);
                    BLo[k16][ni][r] = pack_bf2(w0 - h0, w1 - h1);
                }
    }

    // ---- init: zero h_{-1} (buffer 1) slice, reset own flag ----
    const int gb  = tid & 31;
    const int gdl = (tid >> 5) & 7;
    if (tid < 256) {
        g_hHi[1][gb * DD + d0 + gdl] = __float2bfloat16(0.0f);
        g_hLo[1][gb * DD + d0 + gdl] = __float2bfloat16(0.0f);
    }
    if (tid == 0) g_flag[blockIdx.x][0] = 0ULL;
    float c_reg = 0.0f;

    __threadfence();
    __syncthreads();

    // ---- initial full grid barrier (monotonic counter, epoch-derived) ----
    if (tid == 0) {
        u64 old = atomicAdd(&g_bar, 1ULL);
        u64 bs  = old - (old & (u64)(NBLK - 1));
        u64 tgt = bs + NBLK;
        while (*((volatile u64*)&g_bar) < tgt) { }
        __threadfence();
    }
    __syncthreads();

    const uint32_t sHi_u = smem_u32(sHi);
    const uint32_t sLo_u = smem_u32(sLo);

    for (int s = 0; s < SS; s++) {
        const int rpar = (s + 1) & 1;    // buffer holding h_{s-1}
        const int wpar = s & 1;          // buffer for h_s

        // xp prefetch (gate threads only; hide L2 latency across the step)
        float xp0, xp1, xp2, xp3;
        if (tid < 256) {
            const float* xpp = g_xp + ((size_t)s * BB + gb) * EE + d0 + gdl;
            xp0 = __ldg(xpp);
            xp1 = __ldg(xpp + 1024);
            xp2 = __ldg(xpp + 2048);
            xp3 = __ldg(xpp + 3072);
        }

        // ---- wait for my producer (acquire), then stage its data ----
        {
            u64 v;
            do {
                asm volatile("ld.acquire.gpu.global.u64 %0, [%1];"
                             : "=l"(v) : "l"(pollp));
            } while (v < (u64)s);
        }
        const __nv_bfloat16* srcHi = g_hHi[rpar];
        const __nv_bfloat16* srcLo = g_hLo[rpar];
        #pragma unroll 8
        for (int it = 0; it < 16; it++) {
            int idx = it * 64 + lt2;
            int arr = idx >> 9, rem = idx & 511;
            int b = rem >> 4, k8 = rem & 15;
            const __nv_bfloat16* src = (arr ? srcLo : srcHi) + b * DD + kbase + k8 * 8;
            uint4 v = __ldcg((const uint4*)src);
            __nv_bfloat16* dst = (arr ? sLo : sHi) + b * H_STRIDE + kbase + k8 * 8;
            *(uint4*)dst = v;
        }
        asm volatile("bar.sync %0, 64;" :: "r"(1 + ks) : "memory");

        // ---- MMA: bf16x3, one f32 acc ----
        float c[2][2][4];
        #pragma unroll
        for (int mi = 0; mi < 2; mi++)
            #pragma unroll
            for (int ni = 0; ni < 2; ni++)
                #pragma unroll
                for (int q = 0; q < 4; q++) c[mi][ni][q] = 0.0f;

        #pragma unroll
        for (int k16 = 0; k16 < 8; k16++) {
            const int kcol = kbase + k16 * 16;
            #pragma unroll
            for (int mi = 0; mi < 2; mi++) {
                uint32_t off = (uint32_t)(((mi * 16 + (lane & 15)) * H_STRIDE
                                           + kcol + (lane >> 4) * 8) * 2);
                uint32_t a0, a1, a2, a3, l0, l1, l2, l3;
                LDMATRIX_X4(a0, a1, a2, a3, sHi_u + off);
                LDMATRIX_X4(l0, l1, l2, l3, sLo_u + off);
                #pragma unroll
                for (int ni = 0; ni < 2; ni++) {
                    uint32_t b0 = BHi[k16][ni][0], b1 = BHi[k16][ni][1];
                    uint32_t c0 = BLo[k16][ni][0], c1 = BLo[k16][ni][1];
                    MMA_BF16(c[mi][ni], a0, a1, a2, a3, b0, b1);
                    MMA_BF16(c[mi][ni], l0, l1, l2, l3, b0, b1);
                    MMA_BF16(c[mi][ni], a0, a1, a2, a3, c0, c1);
                }
            }
        }

        // ---- store partials: red[wpar][ks][j][b] ----
        {
            float* rb = red + wpar * 8192 + ks * 1024;
            #pragma unroll
            for (int mi = 0; mi < 2; mi++)
                #pragma unroll
                for (int ni = 0; ni < 2; ni++) {
                    int row0 = mi * 16 + (lane >> 2);
                    int col0 = nh * 16 + ni * 8 + (lane & 3) * 2;
                    rb[col0 * 32 + row0]           = c[mi][ni][0];
                    rb[(col0 + 1) * 32 + row0]     = c[mi][ni][1];
                    rb[col0 * 32 + row0 + 8]       = c[mi][ni][2];
                    rb[(col0 + 1) * 32 + row0 + 8] = c[mi][ni][3];
                }
        }
        __syncthreads();   // all red stored; all 128 flags >= s observed CTA-wide

        // ---- gates tail (warps 0-7 only); warps 8-15 go straight to s+1 ----
        if (tid < 256) {
            const float* rp = red + wpar * 8192;
            float z0 = xp0, z1 = xp1, z2 = xp2, z3 = xp3;
            #pragma unroll
            for (int kk = 0; kk < 8; kk++) {
                const float* rb = rp + kk * 1024;
                z0 += rb[(0 * 8 + gdl) * 32 + gb];
                z1 += rb[(1 * 8 + gdl) * 32 + gb];
                z2 += rb[(2 * 8 + gdl) * 32 + gb];
                z3 += rb[(3 * 8 + gdl) * 32 + gb];
            }
            float it = sigf(z0), ft = sigf(z1), ot = sigf(z2);
            float gt = tanhf_fast(z3);
            float ct = sigf(ft * c_reg + it * gt);   // nonstandard cell (matches ref)
            float ht = tanhf_fast(ct) * ot;
            c_reg = ct;
            out[((size_t)gb * SS + s) * DD + d0 + gdl] = ht;
            __nv_bfloat16 hh = __float2bfloat16(ht);
            __nv_bfloat16 hl = __float2bfloat16(ht - __bfloat162float(hh));
            g_hHi[wpar][gb * DD + d0 + gdl] = hh;
            g_hLo[wpar][gb * DD + d0 + gdl] = hl;

            // gate-group barrier, then publish flag (release)
            asm volatile("bar.sync 10, 256;" ::: "memory");
            if (tid == 0) {
                asm volatile("st.release.gpu.global.u64 [%0], %1;"
                             :: "l"(&g_flag[blockIdx.x][0]), "l"((u64)(s + 1)) : "memory");
            }
        }
    }
}

// =====================================================================
// Input order: 0:seq, 1:Ui, 2:Wi, 3:Uf, 4:Wf, 5:Uo, 6:Wo, 7:Ug, 8:Wg,
//              9:bi, 10:bf, 11:bo, 12:bg
// =====================================================================
extern "C" void kernel_launch(void* const* d_in, const int* in_sizes, int n_in,
                              void* d_out, int out_size)
{
    const float* X  = (const float*)d_in[0];
    const float* Ui = (const float*)d_in[1];
    const float* Wi = (const float*)d_in[2];
    const float* Uf = (const float*)d_in[3];
    const float* Wf = (const float*)d_in[4];
    const float* Uo = (const float*)d_in[5];
    const float* Wo = (const float*)d_in[6];
    const float* Ug = (const float*)d_in[7];
    const float* Wg = (const float*)d_in[8];
    const float* bi = (const float*)d_in[9];
    const float* bf = (const float*)d_in[10];
    const float* bo = (const float*)d_in[11];
    const float* bg = (const float*)d_in[12];
    float* out = (float*)d_out;

    // Prep: split X, transpose+split U
    splitX_kernel<<<(BB * SS * DD) / (256 * 4), 256>>>(X);
    dim3 gt(32, 32, 4);
    transU_kernel<<<gt, 256>>>(Ui, Uf, Uo, Ug);

    // x_proj GEMM (HMMA bf16x3)
    cudaFuncSetAttribute(xproj_mma,
                         cudaFuncAttributeMaxDynamicSharedMemorySize, XJ_SMEM);
    dim3 g1(EE / 64, (BB * SS) / 128);   // (64, 128)
    xproj_mma<<<g1, 256, XJ_SMEM>>>(bi, bf, bo, bg);

    // Recurrence (HMMA, persistent, flag-based sync, decoupled tail)
    cudaFuncSetAttribute(lstm_rec_mma,
                         cudaFuncAttributeMaxDynamicSharedMemorySize, REC_SMEM_BYTES);
    lstm_rec_mma<<<NBLK, 512, REC_SMEM_BYTES>>>(Wi, Wf, Wo, Wg, out);
}

// round 13
// speedup vs baseline: 2.7357x; 1.3754x over previous
#include <cuda_runtime.h>
#include <cuda_fp16.h>
#include <cuda_bf16.h>
#include <math.h>
#include <stdint.h>

// Problem constants
#define BB   32
#define SS   512
#define DD   1024
#define EE   4096          // 4*D
#define NBLK 128           // recurrence CTAs (all co-resident, 1/SM)

typedef unsigned long long u64;

// ---------- scratch (static __device__: no runtime allocation) ----------
__device__ __align__(16) float g_xp[(size_t)SS * BB * EE];       // x_proj [s][b][e]
__device__ __align__(16) __half g_Xh [(size_t)BB * SS * DD];     // X fp16
__device__ __align__(16) __half g_Uthi[(size_t)EE * DD];         // U^T hi [e][k]
__device__ __align__(16) __half g_Utlo[(size_t)EE * DD];         // U^T lo [e][k]
__device__ __align__(16) __half g_hH[2][BB * DD];                // h fp16, [par][b][d]
__device__ u64 g_bar;                                            // init barrier (monotonic)
__device__ u64 g_flag[NBLK][16];                                 // per-CTA step flags, 128B pad

__device__ __forceinline__ uint32_t smem_u32(const void* p) {
    uint32_t a;
    asm("{ .reg .u64 t; cvta.to.shared.u64 t, %1; cvt.u32.u64 %0, t; }" : "=r"(a) : "l"(p));
    return a;
}

__device__ __forceinline__ float sigf(float x) {
    float e = __expf(-x);
    float y; asm("rcp.approx.f32 %0, %1;" : "=f"(y) : "f"(1.0f + e));
    return y;
}

__device__ __forceinline__ float tanhf_fast(float x) {
    float e = __expf(2.0f * x);
    return 1.0f - __fdividef(2.0f, e + 1.0f);   // exact limits at +/-inf
}

__device__ __forceinline__ uint32_t pack_hf2(float a, float b) {
    __half h0 = __float2half_rn(a), h1 = __float2half_rn(b);
    uint16_t u0, u1;
    memcpy(&u0, &h0, 2); memcpy(&u1, &h1, 2);
    return (uint32_t)u0 | ((uint32_t)u1 << 16);
}

#define LDMATRIX_X4(a0, a1, a2, a3, addr) \
    asm volatile("ldmatrix.sync.aligned.m8n8.x4.shared.b16 {%0,%1,%2,%3}, [%4];" \
                 : "=r"(a0), "=r"(a1), "=r"(a2), "=r"(a3) : "r"(addr))

#define MMA_FP16(c, a0, a1, a2, a3, b0, b1) \
    asm volatile("mma.sync.aligned.m16n8k16.row.col.f32.f16.f16.f32 " \
                 "{%0,%1,%2,%3}, {%4,%5,%6,%7}, {%8,%9}, {%0,%1,%2,%3};" \
                 : "+f"((c)[0]), "+f"((c)[1]), "+f"((c)[2]), "+f"((c)[3]) \
                 : "r"(a0), "r"(a1), "r"(a2), "r"(a3), "r"(b0), "r"(b1))

// =====================================================================
// Prep 1: X (fp32) -> fp16, same layout (m=b*512+s rows)
// =====================================================================
__global__ void __launch_bounds__(256) splitX_kernel(const float* __restrict__ X)
{
    size_t i = ((size_t)blockIdx.x * 256 + threadIdx.x) * 4;
    float4 v = *(const float4*)(X + i);
    __half2 p01, p23;
    p01.x = __float2half_rn(v.x); p01.y = __float2half_rn(v.y);
    p23.x = __float2half_rn(v.z); p23.y = __float2half_rn(v.w);
    *(__half2*)(g_Xh + i)     = p01;
    *(__half2*)(g_Xh + i + 2) = p23;
}

// =====================================================================
// Prep 2: transpose + split U (fp16 hi/lo): g_Ut[e][k] = Ugate[k][col]
// =====================================================================
__global__ void __launch_bounds__(256) transU_kernel(
    const float* __restrict__ Ui, const float* __restrict__ Uf,
    const float* __restrict__ Uo, const float* __restrict__ Ug)
{
    __shared__ float t[32][33];
    const int gate = blockIdx.z;
    const float* U = (gate == 0) ? Ui : (gate == 1) ? Uf : (gate == 2) ? Uo : Ug;
    const int col0 = blockIdx.x * 32;
    const int k0   = blockIdx.y * 32;
    const int tx = threadIdx.x & 31, ty = threadIdx.x >> 5;

    #pragma unroll
    for (int rr = 0; rr < 4; rr++)
        t[ty + rr * 8][tx] = U[(size_t)(k0 + ty + rr * 8) * 1024 + col0 + tx];
    __syncthreads();
    #pragma unroll
    for (int rr = 0; rr < 4; rr++) {
        int c = ty + rr * 8;
        float v = t[tx][c];
        __half hi = __float2half_rn(v);
        size_t dst = (size_t)(gate * 1024 + col0 + c) * 1024 + k0 + tx;
        g_Uthi[dst] = hi;
        g_Utlo[dst] = __float2half_rn(v - __half2float(hi));
    }
}

// =====================================================================
// Kernel 1: x_proj via HMMA fp16x2. CTA tile 128m x 64n, 8 warps.
// SMEM: Ah[128][72] + Bhi/Blo[64][72] halves = 36864 B
// =====================================================================
#define XJ_SMEM ((128 + 64 + 64) * 72 * 2)

__global__ void __launch_bounds__(256) xproj_mma(
    const float* __restrict__ bi, const float* __restrict__ bf_,
    const float* __restrict__ bo, const float* __restrict__ bg)
{
    extern __shared__ __half xsm[];
    __half* Ah  = xsm;                 // [128][72]
    __half* Bhi = Ah + 128 * 72;       // [64][72]
    __half* Blo = Bhi + 64 * 72;

    const int tid  = threadIdx.x;
    const int wid  = tid >> 5;
    const int lane = tid & 31;
    const int n0   = blockIdx.x * 64;
    const int m0   = blockIdx.y * 128;
    const int gate = n0 >> 10;
    const float* bp = (gate == 0) ? bi : (gate == 1) ? bf_ : (gate == 2) ? bo : bg;

    const int mi2 = wid & 3;
    const int nh2 = wid >> 2;

    const uint32_t AhU  = smem_u32(Ah);
    const uint32_t BhiU = smem_u32(Bhi), BloU = smem_u32(Blo);

    float c[2][4][4];
    #pragma unroll
    for (int mi = 0; mi < 2; mi++)
        #pragma unroll
        for (int nb = 0; nb < 4; nb++)
            #pragma unroll
            for (int q = 0; q < 4; q++) c[mi][nb][q] = 0.0f;

    for (int kc = 0; kc < 1024; kc += 64) {
        __syncthreads();
        // A: 128 rows x 8 u4 = 1024 u4 -> 4 iters
        #pragma unroll
        for (int it = 0; it < 4; it++) {
            int idx = it * 256 + tid;
            int row = idx >> 3, k8 = idx & 7;
            size_t src = (size_t)(m0 + row) * 1024 + kc + k8 * 8;
            *(uint4*)&Ah[row * 72 + k8 * 8] = *(const uint4*)&g_Xh[src];
        }
        // B: 64 rows x 8 u4 x 2 arrays = 1024 u4 -> 4 iters
        #pragma unroll
        for (int it = 0; it < 2; it++) {
            int idx = it * 256 + tid;
            int row = idx >> 3, k8 = idx & 7;
            size_t src = (size_t)(n0 + row) * 1024 + kc + k8 * 8;
            *(uint4*)&Bhi[row * 72 + k8 * 8] = *(const uint4*)&g_Uthi[src];
            *(uint4*)&Blo[row * 72 + k8 * 8] = *(const uint4*)&g_Utlo[src];
        }
        __syncthreads();

        #pragma unroll
        for (int k16 = 0; k16 < 4; k16++) {
            const int kcol = k16 * 16;
            uint32_t ah[2][4], bh[2][4], bl[2][4];
            #pragma unroll
            for (int mi = 0; mi < 2; mi++) {
                uint32_t off = (uint32_t)(((mi2 * 32 + mi * 16 + (lane & 15)) * 72
                                           + kcol + (lane >> 4) * 8) * 2);
                LDMATRIX_X4(ah[mi][0], ah[mi][1], ah[mi][2], ah[mi][3], AhU + off);
            }
            #pragma unroll
            for (int nb2 = 0; nb2 < 2; nb2++) {
                int rowb = nh2 * 32 + nb2 * 16 + ((lane >> 4) << 3) + (lane & 7);
                int koff = kcol + ((lane >> 3) & 1) * 8;
                uint32_t off = (uint32_t)((rowb * 72 + koff) * 2);
                LDMATRIX_X4(bh[nb2][0], bh[nb2][1], bh[nb2][2], bh[nb2][3], BhiU + off);
                LDMATRIX_X4(bl[nb2][0], bl[nb2][1], bl[nb2][2], bl[nb2][3], BloU + off);
            }
            #pragma unroll
            for (int mi = 0; mi < 2; mi++)
                #pragma unroll
                for (int nb = 0; nb < 4; nb++) {
                    uint32_t b0 = bh[nb >> 1][(nb & 1) * 2];
                    uint32_t b1 = bh[nb >> 1][(nb & 1) * 2 + 1];
                    uint32_t c0 = bl[nb >> 1][(nb & 1) * 2];
                    uint32_t c1 = bl[nb >> 1][(nb & 1) * 2 + 1];
                    MMA_FP16(c[mi][nb], ah[mi][0], ah[mi][1], ah[mi][2], ah[mi][3], b0, b1);
                    MMA_FP16(c[mi][nb], ah[mi][0], ah[mi][1], ah[mi][2], ah[mi][3], c0, c1);
                }
        }
    }

    #pragma unroll
    for (int mi = 0; mi < 2; mi++)
        #pragma unroll
        for (int nb = 0; nb < 4; nb++) {
            int e_loc = nh2 * 32 + nb * 8 + (lane & 3) * 2;
            float bias0 = bp[(n0 & 1023) + e_loc];
            float bias1 = bp[(n0 & 1023) + e_loc + 1];
            #pragma unroll
            for (int h = 0; h < 2; h++) {
                int m = m0 + mi2 * 32 + mi * 16 + (lane >> 2) + h * 8;
                int s = m & 511, b = m >> 9;
                float2 v = {c[mi][nb][h * 2] + bias0, c[mi][nb][h * 2 + 1] + bias1};
                *(float2*)&g_xp[((size_t)s * BB + b) * EE + n0 + e_loc] = v;
            }
        }
}

// =====================================================================
// Kernel 2: HMMA recurrence, fp16 h x fp16x2 W, flag-sync, decoupled tail.
// 128 persistent CTAs x 512 threads. CTA owns 32 z-cols (4 gates x 8 d).
// Warp-pair ks consumes K-chunk [128ks,128ks+128) = producers 16ks..16ks+15.
// SMEM: h [32][1032] half (66048) + red [2][8][32][32] f32 (65536) = 131584
// =====================================================================
#define H_STRIDE 1032
#define REC_SMEM_BYTES (32 * H_STRIDE * 2 + 2 * 8 * 32 * 32 * 4)

__global__ void __launch_bounds__(512, 1) lstm_rec_mma(
    const float* __restrict__ Wi, const float* __restrict__ Wf,
    const float* __restrict__ Wo, const float* __restrict__ Wg,
    float* __restrict__ out)
{
    extern __shared__ char sm[];
    __half* sH = (__half*)sm;                                  // [32][1032]
    float* red = (float*)(sm + 32 * H_STRIDE * 2);             // [2 par][8 ks][32 j][32 b]

    const int tid  = threadIdx.x;
    const int wid  = tid >> 5;
    const int lane = tid & 31;
    const int d0   = blockIdx.x * 8;

    const int ks = wid >> 1;          // K-chunk 0..7 (128 wide)
    const int nh = wid & 1;           // N-half
    const int kbase = ks << 7;
    const int lt2 = tid & 63;

    // Flag this thread polls: the producer of the d-slice it loads in fill
    const u64* pollp = &g_flag[16 * ks + (lt2 & 15)][0];

    // ---- W fragments resident in registers (fp16 hi + lo) ----
    uint32_t WHi[8][2][2], WLo[8][2][2];
    {
        const float* Wm[4] = {Wi, Wf, Wo, Wg};
        #pragma unroll
        for (int k16 = 0; k16 < 8; k16++)
            #pragma unroll
            for (int ni = 0; ni < 2; ni++)
                #pragma unroll
                for (int r = 0; r < 2; r++) {
                    int j = nh * 16 + ni * 8 + (lane >> 2);
                    int k0 = kbase + k16 * 16 + (lane & 3) * 2 + r * 8;
                    const float* wp = Wm[j >> 3] + (size_t)k0 * 1024 + d0 + (j & 7);
                    float w0 = __ldg(wp), w1 = __ldg(wp + 1024);
                    float h0 = __half2float(__float2half_rn(w0));
                    float h1 = __half2float(__float2half_rn(w1));
                    WHi[k16][ni][r] = pack_hf2(w0, w1);
                    WLo[k16][ni][r] = pack_hf2(w0 - h0, w1 - h1);
                }
    }

    // ---- init: zero h_{-1} (buffer 1) slice, reset own flag ----
    const int gb  = tid & 31;
    const int gdl = (tid >> 5) & 7;
    if (tid < 256) g_hH[1][gb * DD + d0 + gdl] = __float2half(0.0f);
    if (tid == 0) g_flag[blockIdx.x][0] = 0ULL;
    float c_reg = 0.0f;

    __threadfence();
    __syncthreads();

    // ---- initial full grid barrier (monotonic counter, epoch-derived) ----
    if (tid == 0) {
        u64 old = atomicAdd(&g_bar, 1ULL);
        u64 bs  = old - (old & (u64)(NBLK - 1));
        u64 tgt = bs + NBLK;
        while (*((volatile u64*)&g_bar) < tgt) { }
        __threadfence();
    }
    __syncthreads();

    const uint32_t sH_u = smem_u32(sH);

    for (int s = 0; s < SS; s++) {
        const int rpar = (s + 1) & 1;    // buffer holding h_{s-1}
        const int wpar = s & 1;          // buffer for h_s

        // xp prefetch (gate threads only; hide L2 latency across the step)
        float xp0, xp1, xp2, xp3;
        if (tid < 256) {
            const float* xpp = g_xp + ((size_t)s * BB + gb) * EE + d0 + gdl;
            xp0 = __ldg(xpp);
            xp1 = __ldg(xpp + 1024);
            xp2 = __ldg(xpp + 2048);
            xp3 = __ldg(xpp + 3072);
        }

        // ---- wait for my producer (acquire), then stage its data ----
        {
            u64 v;
            do {
                asm volatile("ld.acquire.gpu.global.u64 %0, [%1];"
                             : "=l"(v) : "l"(pollp));
            } while (v < (u64)s);
        }
        // fill: 32 b x 128 k halves = 512 u4 over 64 threads = 8 iters
        const __half* srcH = g_hH[rpar];
        #pragma unroll 8
        for (int it = 0; it < 8; it++) {
            int idx = it * 64 + lt2;
            int b = idx >> 4, k8 = idx & 15;
            uint4 v = __ldcg((const uint4*)(srcH + b * DD + kbase + k8 * 8));
            *(uint4*)(sH + b * H_STRIDE + kbase + k8 * 8) = v;
        }
        asm volatile("bar.sync %0, 64;" :: "r"(1 + ks) : "memory");

        // ---- MMA: 2 passes (A*WHi + A*WLo), one f32 acc ----
        float c[2][2][4];
        #pragma unroll
        for (int mi = 0; mi < 2; mi++)
            #pragma unroll
            for (int ni = 0; ni < 2; ni++)
                #pragma unroll
                for (int q = 0; q < 4; q++) c[mi][ni][q] = 0.0f;

        #pragma unroll
        for (int k16 = 0; k16 < 8; k16++) {
            const int kcol = kbase + k16 * 16;
            #pragma unroll
            for (int mi = 0; mi < 2; mi++) {
                uint32_t off = (uint32_t)(((mi * 16 + (lane & 15)) * H_STRIDE
                                           + kcol + (lane >> 4) * 8) * 2);
                uint32_t a0, a1, a2, a3;
                LDMATRIX_X4(a0, a1, a2, a3, sH_u + off);
                #pragma unroll
                for (int ni = 0; ni < 2; ni++) {
                    MMA_FP16(c[mi][ni], a0, a1, a2, a3,
                             WHi[k16][ni][0], WHi[k16][ni][1]);
                    MMA_FP16(c[mi][ni], a0, a1, a2, a3,
                             WLo[k16][ni][0], WLo[k16][ni][1]);
                }
            }
        }

        // ---- store partials: red[wpar][ks][j][b] ----
        {
            float* rb = red + wpar * 8192 + ks * 1024;
            #pragma unroll
            for (int mi = 0; mi < 2; mi++)
                #pragma unroll
                for (int ni = 0; ni < 2; ni++) {
                    int row0 = mi * 16 + (lane >> 2);
                    int col0 = nh * 16 + ni * 8 + (lane & 3) * 2;
                    rb[col0 * 32 + row0]           = c[mi][ni][0];
                    rb[(col0 + 1) * 32 + row0]     = c[mi][ni][1];
                    rb[col0 * 32 + row0 + 8]       = c[mi][ni][2];
                    rb[(col0 + 1) * 32 + row0 + 8] = c[mi][ni][3];
                }
        }
        __syncthreads();   // all red stored; all 128 flags >= s observed CTA-wide

        // ---- gates tail (warps 0-7 only); warps 8-15 go straight to s+1 ----
        if (tid < 256) {
            const float* rp = red + wpar * 8192;
            float z0 = xp0, z1 = xp1, z2 = xp2, z3 = xp3;
            #pragma unroll
            for (int kk = 0; kk < 8; kk++) {
                const float* rb = rp + kk * 1024;
                z0 += rb[(0 * 8 + gdl) * 32 + gb];
                z1 += rb[(1 * 8 + gdl) * 32 + gb];
                z2 += rb[(2 * 8 + gdl) * 32 + gb];
                z3 += rb[(3 * 8 + gdl) * 32 + gb];
            }
            float it = sigf(z0), ft = sigf(z1), ot = sigf(z2);
            float gt = tanhf_fast(z3);
            float ct = sigf(ft * c_reg + it * gt);   // nonstandard cell (matches ref)
            float ht = tanhf_fast(ct) * ot;
            c_reg = ct;
            out[((size_t)gb * SS + s) * DD + d0 + gdl] = ht;
            g_hH[wpar][gb * DD + d0 + gdl] = __float2half_rn(ht);

            // gate-group barrier, then publish flag (release)
            asm volatile("bar.sync 10, 256;" ::: "memory");
            if (tid == 0) {
                asm volatile("st.release.gpu.global.u64 [%0], %1;"
                             :: "l"(&g_flag[blockIdx.x][0]), "l"((u64)(s + 1)) : "memory");
            }
        }
    }
}

// =====================================================================
// Input order: 0:seq, 1:Ui, 2:Wi, 3:Uf, 4:Wf, 5:Uo, 6:Wo, 7:Ug, 8:Wg,
//              9:bi, 10:bf, 11:bo, 12:bg
// =====================================================================
extern "C" void kernel_launch(void* const* d_in, const int* in_sizes, int n_in,
                              void* d_out, int out_size)
{
    const float* X  = (const float*)d_in[0];
    const float* Ui = (const float*)d_in[1];
    const float* Wi = (const float*)d_in[2];
    const float* Uf = (const float*)d_in[3];
    const float* Wf = (const float*)d_in[4];
    const float* Uo = (const float*)d_in[5];
    const float* Wo = (const float*)d_in[6];
    const float* Ug = (const float*)d_in[7];
    const float* Wg = (const float*)d_in[8];
    const float* bi = (const float*)d_in[9];
    const float* bf = (const float*)d_in[10];
    const float* bo = (const float*)d_in[11];
    const float* bg = (const float*)d_in[12];
    float* out = (float*)d_out;

    // Prep: X -> fp16, transpose+split U -> fp16 hi/lo
    splitX_kernel<<<(BB * SS * DD) / (256 * 4), 256>>>(X);
    dim3 gt(32, 32, 4);
    transU_kernel<<<gt, 256>>>(Ui, Uf, Uo, Ug);

    // x_proj GEMM (HMMA fp16x2)
    cudaFuncSetAttribute(xproj_mma,
                         cudaFuncAttributeMaxDynamicSharedMemorySize, XJ_SMEM);
    dim3 g1(EE / 64, (BB * SS) / 128);   // (64, 128)
    xproj_mma<<<g1, 256, XJ_SMEM>>>(bi, bf, bo, bg);

    // Recurrence (HMMA fp16, persistent, flag-based sync, decoupled tail)
    cudaFuncSetAttribute(lstm_rec_mma,
                         cudaFuncAttributeMaxDynamicSharedMemorySize, REC_SMEM_BYTES);
    lstm_rec_mma<<<NBLK, 512, REC_SMEM_BYTES>>>(Wi, Wf, Wo, Wg, out);
}

// round 14
// speedup vs baseline: 3.0875x; 1.1286x over previous
#include <cuda_runtime.h>
#include <cuda_fp16.h>
#include <math.h>
#include <stdint.h>

// Problem constants
#define BB   32
#define SS   512
#define DD   1024
#define EE   4096          // 4*D
#define NBLK 128           // recurrence CTAs (all co-resident, 1/SM)

typedef unsigned long long u64;

// ---------- scratch (static __device__: no runtime allocation) ----------
__device__ __align__(16) float g_xp[(size_t)SS * BB * EE];       // x_proj [s][b][e]
__device__ __align__(16) __half g_Xh [(size_t)BB * SS * DD];     // X fp16
__device__ __align__(16) __half g_Uth[(size_t)EE * DD];          // U^T fp16 [e][k]
__device__ __align__(16) __half g_hH[2][BB * DD];                // h fp16, [par][b][d]
__device__ u64 g_bar;                                            // init barrier (monotonic)
__device__ u64 g_flag[NBLK][16];                                 // per-CTA step flags, 128B pad

__device__ __forceinline__ uint32_t smem_u32(const void* p) {
    uint32_t a;
    asm("{ .reg .u64 t; cvta.to.shared.u64 t, %1; cvt.u32.u64 %0, t; }" : "=r"(a) : "l"(p));
    return a;
}

__device__ __forceinline__ float sigf(float x) {
    float e = __expf(-x);
    float y; asm("rcp.approx.f32 %0, %1;" : "=f"(y) : "f"(1.0f + e));
    return y;
}

__device__ __forceinline__ float tanhf_fast(float x) {
    float e = __expf(2.0f * x);
    return 1.0f - __fdividef(2.0f, e + 1.0f);   // exact limits at +/-inf
}

__device__ __forceinline__ uint32_t pack_hf2(float a, float b) {
    __half h0 = __float2half_rn(a), h1 = __float2half_rn(b);
    uint16_t u0, u1;
    memcpy(&u0, &h0, 2); memcpy(&u1, &h1, 2);
    return (uint32_t)u0 | ((uint32_t)u1 << 16);
}

#define LDMATRIX_X4(a0, a1, a2, a3, addr) \
    asm volatile("ldmatrix.sync.aligned.m8n8.x4.shared.b16 {%0,%1,%2,%3}, [%4];" \
                 : "=r"(a0), "=r"(a1), "=r"(a2), "=r"(a3) : "r"(addr))

#define MMA_FP16(c, a0, a1, a2, a3, b0, b1) \
    asm volatile("mma.sync.aligned.m16n8k16.row.col.f32.f16.f16.f32 " \
                 "{%0,%1,%2,%3}, {%4,%5,%6,%7}, {%8,%9}, {%0,%1,%2,%3};" \
                 : "+f"((c)[0]), "+f"((c)[1]), "+f"((c)[2]), "+f"((c)[3]) \
                 : "r"(a0), "r"(a1), "r"(a2), "r"(a3), "r"(b0), "r"(b1))

// =====================================================================
// Prep 1: X (fp32) -> fp16, same layout (m=b*512+s rows)
// =====================================================================
__global__ void __launch_bounds__(256) splitX_kernel(const float* __restrict__ X)
{
    size_t i = ((size_t)blockIdx.x * 256 + threadIdx.x) * 4;
    float4 v = *(const float4*)(X + i);
    __half2 p01, p23;
    p01.x = __float2half_rn(v.x); p01.y = __float2half_rn(v.y);
    p23.x = __float2half_rn(v.z); p23.y = __float2half_rn(v.w);
    *(__half2*)(g_Xh + i)     = p01;
    *(__half2*)(g_Xh + i + 2) = p23;
}

// =====================================================================
// Prep 2: transpose U -> fp16: g_Uth[e=gate*1024+col][k] = Ugate[k][col]
// =====================================================================
__global__ void __launch_bounds__(256) transU_kernel(
    const float* __restrict__ Ui, const float* __restrict__ Uf,
    const float* __restrict__ Uo, const float* __restrict__ Ug)
{
    __shared__ float t[32][33];
    const int gate = blockIdx.z;
    const float* U = (gate == 0) ? Ui : (gate == 1) ? Uf : (gate == 2) ? Uo : Ug;
    const int col0 = blockIdx.x * 32;
    const int k0   = blockIdx.y * 32;
    const int tx = threadIdx.x & 31, ty = threadIdx.x >> 5;

    #pragma unroll
    for (int rr = 0; rr < 4; rr++)
        t[ty + rr * 8][tx] = U[(size_t)(k0 + ty + rr * 8) * 1024 + col0 + tx];
    __syncthreads();
    #pragma unroll
    for (int rr = 0; rr < 4; rr++) {
        int c = ty + rr * 8;
        g_Uth[(size_t)(gate * 1024 + col0 + c) * 1024 + k0 + tx] =
            __float2half_rn(t[tx][c]);
    }
}

// =====================================================================
// Kernel 1: x_proj via HMMA fp16 (single pass). CTA 128m x 64n, 8 warps.
// SMEM: Ah[128][72] + Bh[64][72] halves = 27648 B
// =====================================================================
#define XJ_SMEM ((128 + 64) * 72 * 2)

__global__ void __launch_bounds__(256) xproj_mma(
    const float* __restrict__ bi, const float* __restrict__ bf_,
    const float* __restrict__ bo, const float* __restrict__ bg)
{
    extern __shared__ __half xsm[];
    __half* Ah = xsm;                 // [128][72]
    __half* Bh = Ah + 128 * 72;       // [64][72]

    const int tid  = threadIdx.x;
    const int wid  = tid >> 5;
    const int lane = tid & 31;
    const int n0   = blockIdx.x * 64;
    const int m0   = blockIdx.y * 128;
    const int gate = n0 >> 10;
    const float* bp = (gate == 0) ? bi : (gate == 1) ? bf_ : (gate == 2) ? bo : bg;

    const int mi2 = wid & 3;
    const int nh2 = wid >> 2;

    const uint32_t AhU = smem_u32(Ah);
    const uint32_t BhU = smem_u32(Bh);

    float c[2][4][4];
    #pragma unroll
    for (int mi = 0; mi < 2; mi++)
        #pragma unroll
        for (int nb = 0; nb < 4; nb++)
            #pragma unroll
            for (int q = 0; q < 4; q++) c[mi][nb][q] = 0.0f;

    for (int kc = 0; kc < 1024; kc += 64) {
        __syncthreads();
        #pragma unroll
        for (int it = 0; it < 4; it++) {
            int idx = it * 256 + tid;
            int row = idx >> 3, k8 = idx & 7;
            size_t src = (size_t)(m0 + row) * 1024 + kc + k8 * 8;
            *(uint4*)&Ah[row * 72 + k8 * 8] = *(const uint4*)&g_Xh[src];
        }
        {
            int idx = tid;              // 512 u4 over 256 threads = 2 iters
            int row = idx >> 3, k8 = idx & 7;
            size_t src = (size_t)(n0 + row) * 1024 + kc + k8 * 8;
            *(uint4*)&Bh[row * 72 + k8 * 8] = *(const uint4*)&g_Uth[src];
            idx = 256 + tid;
            row = idx >> 3; k8 = idx & 7;
            src = (size_t)(n0 + row) * 1024 + kc + k8 * 8;
            *(uint4*)&Bh[row * 72 + k8 * 8] = *(const uint4*)&g_Uth[src];
        }
        __syncthreads();

        #pragma unroll
        for (int k16 = 0; k16 < 4; k16++) {
            const int kcol = k16 * 16;
            uint32_t ah[2][4], bh[2][4];
            #pragma unroll
            for (int mi = 0; mi < 2; mi++) {
                uint32_t off = (uint32_t)(((mi2 * 32 + mi * 16 + (lane & 15)) * 72
                                           + kcol + (lane >> 4) * 8) * 2);
                LDMATRIX_X4(ah[mi][0], ah[mi][1], ah[mi][2], ah[mi][3], AhU + off);
            }
            #pragma unroll
            for (int nb2 = 0; nb2 < 2; nb2++) {
                int rowb = nh2 * 32 + nb2 * 16 + ((lane >> 4) << 3) + (lane & 7);
                int koff = kcol + ((lane >> 3) & 1) * 8;
                uint32_t off = (uint32_t)((rowb * 72 + koff) * 2);
                LDMATRIX_X4(bh[nb2][0], bh[nb2][1], bh[nb2][2], bh[nb2][3], BhU + off);
            }
            #pragma unroll
            for (int mi = 0; mi < 2; mi++)
                #pragma unroll
                for (int nb = 0; nb < 4; nb++) {
                    uint32_t b0 = bh[nb >> 1][(nb & 1) * 2];
                    uint32_t b1 = bh[nb >> 1][(nb & 1) * 2 + 1];
                    MMA_FP16(c[mi][nb], ah[mi][0], ah[mi][1], ah[mi][2], ah[mi][3], b0, b1);
                }
        }
    }

    #pragma unroll
    for (int mi = 0; mi < 2; mi++)
        #pragma unroll
        for (int nb = 0; nb < 4; nb++) {
            int e_loc = nh2 * 32 + nb * 8 + (lane & 3) * 2;
            float bias0 = bp[(n0 & 1023) + e_loc];
            float bias1 = bp[(n0 & 1023) + e_loc + 1];
            #pragma unroll
            for (int h = 0; h < 2; h++) {
                int m = m0 + mi2 * 32 + mi * 16 + (lane >> 2) + h * 8;
                int s = m & 511, b = m >> 9;
                float2 v = {c[mi][nb][h * 2] + bias0, c[mi][nb][h * 2 + 1] + bias1};
                *(float2*)&g_xp[((size_t)s * BB + b) * EE + n0 + e_loc] = v;
            }
        }
}

// =====================================================================
// Kernel 2: HMMA recurrence, fp16 h x fp16 W (single pass), flag-sync,
// decoupled gates tail, 2-phase pipelined fill.
// 128 persistent CTAs x 512 threads. CTA owns 32 z-cols (4 gates x 8 d).
// Warp-pair ks consumes K-chunk [128ks,128ks+128) = producers 16ks..16ks+15.
// SMEM: h [32][1032] half (66048) + red [2][8][32][32] f32 (65536)
// =====================================================================
#define H_STRIDE 1032
#define REC_SMEM_BYTES (32 * H_STRIDE * 2 + 2 * 8 * 32 * 32 * 4)

__global__ void __launch_bounds__(512, 1) lstm_rec_mma(
    const float* __restrict__ Wi, const float* __restrict__ Wf,
    const float* __restrict__ Wo, const float* __restrict__ Wg,
    float* __restrict__ out)
{
    extern __shared__ char sm[];
    __half* sH = (__half*)sm;                                  // [32][1032]
    float* red = (float*)(sm + 32 * H_STRIDE * 2);             // [2 par][8 ks][32 j][32 b]

    const int tid  = threadIdx.x;
    const int wid  = tid >> 5;
    const int lane = tid & 31;
    const int d0   = blockIdx.x * 8;

    const int ks = wid >> 1;          // K-chunk 0..7 (128 wide)
    const int nh = wid & 1;           // N-half
    const int kbase = ks << 7;
    const int lt2 = tid & 63;

    // Flag this thread polls: the producer of the d-slice it loads in fill
    const u64* pollp = &g_flag[16 * ks + (lt2 & 15)][0];

    // Fill addressing (per phase: 256 u4 over 64 threads = 4 iters)
    const int fb  = lt2 >> 3;         // base b row group: lt2/8 (0..7) -> with it*8
    const int fk8 = lt2 & 7;          // k8 within phase

    // ---- W fragments resident in registers (fp16 single) ----
    uint32_t WHi[8][2][2];
    {
        const float* Wm[4] = {Wi, Wf, Wo, Wg};
        #pragma unroll
        for (int k16 = 0; k16 < 8; k16++)
            #pragma unroll
            for (int ni = 0; ni < 2; ni++)
                #pragma unroll
                for (int r = 0; r < 2; r++) {
                    int j = nh * 16 + ni * 8 + (lane >> 2);
                    int k0 = kbase + k16 * 16 + (lane & 3) * 2 + r * 8;
                    const float* wp = Wm[j >> 3] + (size_t)k0 * 1024 + d0 + (j & 7);
                    WHi[k16][ni][r] = pack_hf2(__ldg(wp), __ldg(wp + 1024));
                }
    }

    // ---- init: zero h_{-1} (buffer 1) slice, reset own flag ----
    const int gb  = tid & 31;
    const int gdl = (tid >> 5) & 7;
    if (tid < 256) g_hH[1][gb * DD + d0 + gdl] = __float2half(0.0f);
    if (tid == 0) g_flag[blockIdx.x][0] = 0ULL;
    float c_reg = 0.0f;

    __threadfence();
    __syncthreads();

    // ---- initial full grid barrier (monotonic counter, epoch-derived) ----
    if (tid == 0) {
        u64 old = atomicAdd(&g_bar, 1ULL);
        u64 bs  = old - (old & (u64)(NBLK - 1));
        u64 tgt = bs + NBLK;
        while (*((volatile u64*)&g_bar) < tgt) { }
        __threadfence();
    }
    __syncthreads();

    const uint32_t sH_u = smem_u32(sH);

    for (int s = 0; s < SS; s++) {
        const int rpar = (s + 1) & 1;    // buffer holding h_{s-1}
        const int wpar = s & 1;          // buffer for h_s

        // xp prefetch (gate threads only; hide L2 latency across the step)
        float xp0, xp1, xp2, xp3;
        if (tid < 256) {
            const float* xpp = g_xp + ((size_t)s * BB + gb) * EE + d0 + gdl;
            xp0 = __ldg(xpp);
            xp1 = __ldg(xpp + 1024);
            xp2 = __ldg(xpp + 2048);
            xp3 = __ldg(xpp + 3072);
        }

        // ---- wait for my producer (acquire) ----
        {
            u64 v;
            do {
                asm volatile("ld.acquire.gpu.global.u64 %0, [%1];"
                             : "=l"(v) : "l"(pollp));
            } while (v < (u64)s);
        }
        const __half* srcH = g_hH[rpar];

        // ---- phase 0 fill: k-cols [kbase, kbase+64) for all 32 b ----
        #pragma unroll
        for (int it = 0; it < 4; it++) {
            int b = it * 8 + fb;
            uint4 v = __ldcg((const uint4*)(srcH + b * DD + kbase + fk8 * 8));
            *(uint4*)(sH + b * H_STRIDE + kbase + fk8 * 8) = v;
        }
        asm volatile("bar.sync %0, 64;" :: "r"(1 + ks) : "memory");

        // ---- phase 1 LDGs issued into regs (overlap with MMA on phase 0) ----
        uint4 v1[4];
        #pragma unroll
        for (int it = 0; it < 4; it++) {
            int b = it * 8 + fb;
            v1[it] = __ldcg((const uint4*)(srcH + b * DD + kbase + 64 + fk8 * 8));
        }

        float c[2][2][4];
        #pragma unroll
        for (int mi = 0; mi < 2; mi++)
            #pragma unroll
            for (int ni = 0; ni < 2; ni++)
                #pragma unroll
                for (int q = 0; q < 4; q++) c[mi][ni][q] = 0.0f;

        // ---- MMA on phase 0 (k16 0..3) ----
        #pragma unroll
        for (int k16 = 0; k16 < 4; k16++) {
            const int kcol = kbase + k16 * 16;
            #pragma unroll
            for (int mi = 0; mi < 2; mi++) {
                uint32_t off = (uint32_t)(((mi * 16 + (lane & 15)) * H_STRIDE
                                           + kcol + (lane >> 4) * 8) * 2);
                uint32_t a0, a1, a2, a3;
                LDMATRIX_X4(a0, a1, a2, a3, sH_u + off);
                #pragma unroll
                for (int ni = 0; ni < 2; ni++)
                    MMA_FP16(c[mi][ni], a0, a1, a2, a3,
                             WHi[k16][ni][0], WHi[k16][ni][1]);
            }
        }

        // ---- commit phase 1, bar, MMA on phase 1 (k16 4..7) ----
        #pragma unroll
        for (int it = 0; it < 4; it++) {
            int b = it * 8 + fb;
            *(uint4*)(sH + b * H_STRIDE + kbase + 64 + fk8 * 8) = v1[it];
        }
        asm volatile("bar.sync %0, 64;" :: "r"(1 + ks) : "memory");

        #pragma unroll
        for (int k16 = 4; k16 < 8; k16++) {
            const int kcol = kbase + k16 * 16;
            #pragma unroll
            for (int mi = 0; mi < 2; mi++) {
                uint32_t off = (uint32_t)(((mi * 16 + (lane & 15)) * H_STRIDE
                                           + kcol + (lane >> 4) * 8) * 2);
                uint32_t a0, a1, a2, a3;
                LDMATRIX_X4(a0, a1, a2, a3, sH_u + off);
                #pragma unroll
                for (int ni = 0; ni < 2; ni++)
                    MMA_FP16(c[mi][ni], a0, a1, a2, a3,
                             WHi[k16][ni][0], WHi[k16][ni][1]);
            }
        }

        // ---- store partials: red[wpar][ks][j][b] ----
        {
            float* rb = red + wpar * 8192 + ks * 1024;
            #pragma unroll
            for (int mi = 0; mi < 2; mi++)
                #pragma unroll
                for (int ni = 0; ni < 2; ni++) {
                    int row0 = mi * 16 + (lane >> 2);
                    int col0 = nh * 16 + ni * 8 + (lane & 3) * 2;
                    rb[col0 * 32 + row0]           = c[mi][ni][0];
                    rb[(col0 + 1) * 32 + row0]     = c[mi][ni][1];
                    rb[col0 * 32 + row0 + 8]       = c[mi][ni][2];
                    rb[(col0 + 1) * 32 + row0 + 8] = c[mi][ni][3];
                }
        }
        __syncthreads();   // all red stored; all 128 flags >= s observed CTA-wide

        // ---- gates tail (warps 0-7 only); warps 8-15 go straight to s+1 ----
        if (tid < 256) {
            const float* rp = red + wpar * 8192;
            float z0 = xp0, z1 = xp1, z2 = xp2, z3 = xp3;
            #pragma unroll
            for (int kk = 0; kk < 8; kk++) {
                const float* rb = rp + kk * 1024;
                z0 += rb[(0 * 8 + gdl) * 32 + gb];
                z1 += rb[(1 * 8 + gdl) * 32 + gb];
                z2 += rb[(2 * 8 + gdl) * 32 + gb];
                z3 += rb[(3 * 8 + gdl) * 32 + gb];
            }
            float it = sigf(z0), ft = sigf(z1), ot = sigf(z2);
            float gt = tanhf_fast(z3);
            float ct = sigf(ft * c_reg + it * gt);   // nonstandard cell (matches ref)
            float ht = tanhf_fast(ct) * ot;
            c_reg = ct;
            out[((size_t)gb * SS + s) * DD + d0 + gdl] = ht;
            g_hH[wpar][gb * DD + d0 + gdl] = __float2half_rn(ht);

            // gate-group barrier, then publish flag (release)
            asm volatile("bar.sync 10, 256;" ::: "memory");
            if (tid == 0) {
                asm volatile("st.release.gpu.global.u64 [%0], %1;"
                             :: "l"(&g_flag[blockIdx.x][0]), "l"((u64)(s + 1)) : "memory");
            }
        }
    }
}

// =====================================================================
// Input order: 0:seq, 1:Ui, 2:Wi, 3:Uf, 4:Wf, 5:Uo, 6:Wo, 7:Ug, 8:Wg,
//              9:bi, 10:bf, 11:bo, 12:bg
// =====================================================================
extern "C" void kernel_launch(void* const* d_in, const int* in_sizes, int n_in,
                              void* d_out, int out_size)
{
    const float* X  = (const float*)d_in[0];
    const float* Ui = (const float*)d_in[1];
    const float* Wi = (const float*)d_in[2];
    const float* Uf = (const float*)d_in[3];
    const float* Wf = (const float*)d_in[4];
    const float* Uo = (const float*)d_in[5];
    const float* Wo = (const float*)d_in[6];
    const float* Ug = (const float*)d_in[7];
    const float* Wg = (const float*)d_in[8];
    const float* bi = (const float*)d_in[9];
    const float* bf = (const float*)d_in[10];
    const float* bo = (const float*)d_in[11];
    const float* bg = (const float*)d_in[12];
    float* out = (float*)d_out;

    // Prep: X -> fp16, transpose U -> fp16
    splitX_kernel<<<(BB * SS * DD) / (256 * 4), 256>>>(X);
    dim3 gt(32, 32, 4);
    transU_kernel<<<gt, 256>>>(Ui, Uf, Uo, Ug);

    // x_proj GEMM (HMMA fp16)
    cudaFuncSetAttribute(xproj_mma,
                         cudaFuncAttributeMaxDynamicSharedMemorySize, XJ_SMEM);
    dim3 g1(EE / 64, (BB * SS) / 128);   // (64, 128)
    xproj_mma<<<g1, 256, XJ_SMEM>>>(bi, bf, bo, bg);

    // Recurrence (HMMA fp16, persistent, flag-sync, pipelined fill)
    cudaFuncSetAttribute(lstm_rec_mma,
                         cudaFuncAttributeMaxDynamicSharedMemorySize, REC_SMEM_BYTES);
    lstm_rec_mma<<<NBLK, 512, REC_SMEM_BYTES>>>(Wi, Wf, Wo, Wg, out);
}

// round 15
// speedup vs baseline: 3.1581x; 1.0229x over previous
#include <cuda_runtime.h>
#include <cuda_fp16.h>
#include <math.h>
#include <stdint.h>

// Problem constants
#define BB   32
#define SS   512
#define DD   1024
#define EE   4096          // 4*D
#define NBLK 128           // recurrence CTAs (all co-resident, 1/SM)

typedef unsigned long long u64;

// ---------- scratch (static __device__: no runtime allocation) ----------
__device__ __align__(16) float g_xp[(size_t)SS * BB * EE];       // x_proj [s][b][e]
__device__ __align__(16) __half g_Xh [(size_t)BB * SS * DD];     // X fp16
__device__ __align__(16) __half g_Uth[(size_t)EE * DD];          // U^T fp16 [e][k]
__device__ __align__(16) __half g_hH[2][BB * DD];                // h fp16, [par][b][d]
__device__ u64 g_bar;                                            // init barrier (monotonic)
__device__ u64 g_flag[NBLK][16];                                 // per-CTA step flags, 128B pad

__device__ __forceinline__ uint32_t smem_u32(const void* p) {
    uint32_t a;
    asm("{ .reg .u64 t; cvta.to.shared.u64 t, %1; cvt.u32.u64 %0, t; }" : "=r"(a) : "l"(p));
    return a;
}

__device__ __forceinline__ float sigf(float x) {
    float e = __expf(-x);
    float y; asm("rcp.approx.f32 %0, %1;" : "=f"(y) : "f"(1.0f + e));
    return y;
}

__device__ __forceinline__ float tanhf_fast(float x) {
    float e = __expf(2.0f * x);
    return 1.0f - __fdividef(2.0f, e + 1.0f);   // exact limits at +/-inf
}

__device__ __forceinline__ uint32_t pack_hf2(float a, float b) {
    __half h0 = __float2half_rn(a), h1 = __float2half_rn(b);
    uint16_t u0, u1;
    memcpy(&u0, &h0, 2); memcpy(&u1, &h1, 2);
    return (uint32_t)u0 | ((uint32_t)u1 << 16);
}

#define LDMATRIX_X4(a0, a1, a2, a3, addr) \
    asm volatile("ldmatrix.sync.aligned.m8n8.x4.shared.b16 {%0,%1,%2,%3}, [%4];" \
                 : "=r"(a0), "=r"(a1), "=r"(a2), "=r"(a3) : "r"(addr))

#define MMA_FP16(c, a0, a1, a2, a3, b0, b1) \
    asm volatile("mma.sync.aligned.m16n8k16.row.col.f32.f16.f16.f32 " \
                 "{%0,%1,%2,%3}, {%4,%5,%6,%7}, {%8,%9}, {%0,%1,%2,%3};" \
                 : "+f"((c)[0]), "+f"((c)[1]), "+f"((c)[2]), "+f"((c)[3]) \
                 : "r"(a0), "r"(a1), "r"(a2), "r"(a3), "r"(b0), "r"(b1))

// =====================================================================
// Prep 1: X (fp32) -> fp16, same layout (m=b*512+s rows)
// =====================================================================
__global__ void __launch_bounds__(256) splitX_kernel(const float* __restrict__ X)
{
    size_t i = ((size_t)blockIdx.x * 256 + threadIdx.x) * 4;
    float4 v = *(const float4*)(X + i);
    __half2 p01, p23;
    p01.x = __float2half_rn(v.x); p01.y = __float2half_rn(v.y);
    p23.x = __float2half_rn(v.z); p23.y = __float2half_rn(v.w);
    *(__half2*)(g_Xh + i)     = p01;
    *(__half2*)(g_Xh + i + 2) = p23;
}

// =====================================================================
// Prep 2: transpose U -> fp16: g_Uth[e=gate*1024+col][k] = Ugate[k][col]
// =====================================================================
__global__ void __launch_bounds__(256) transU_kernel(
    const float* __restrict__ Ui, const float* __restrict__ Uf,
    const float* __restrict__ Uo, const float* __restrict__ Ug)
{
    __shared__ float t[32][33];
    const int gate = blockIdx.z;
    const float* U = (gate == 0) ? Ui : (gate == 1) ? Uf : (gate == 2) ? Uo : Ug;
    const int col0 = blockIdx.x * 32;
    const int k0   = blockIdx.y * 32;
    const int tx = threadIdx.x & 31, ty = threadIdx.x >> 5;

    #pragma unroll
    for (int rr = 0; rr < 4; rr++)
        t[ty + rr * 8][tx] = U[(size_t)(k0 + ty + rr * 8) * 1024 + col0 + tx];
    __syncthreads();
    #pragma unroll
    for (int rr = 0; rr < 4; rr++) {
        int c = ty + rr * 8;
        g_Uth[(size_t)(gate * 1024 + col0 + c) * 1024 + k0 + tx] =
            __float2half_rn(t[tx][c]);
    }
}

// =====================================================================
// Kernel 1: x_proj via HMMA fp16 (single pass). CTA 128m x 64n, 8 warps.
// =====================================================================
#define XJ_SMEM ((128 + 64) * 72 * 2)

__global__ void __launch_bounds__(256) xproj_mma(
    const float* __restrict__ bi, const float* __restrict__ bf_,
    const float* __restrict__ bo, const float* __restrict__ bg)
{
    extern __shared__ __half xsm[];
    __half* Ah = xsm;                 // [128][72]
    __half* Bh = Ah + 128 * 72;       // [64][72]

    const int tid  = threadIdx.x;
    const int wid  = tid >> 5;
    const int lane = tid & 31;
    const int n0   = blockIdx.x * 64;
    const int m0   = blockIdx.y * 128;
    const int gate = n0 >> 10;
    const float* bp = (gate == 0) ? bi : (gate == 1) ? bf_ : (gate == 2) ? bo : bg;

    const int mi2 = wid & 3;
    const int nh2 = wid >> 2;

    const uint32_t AhU = smem_u32(Ah);
    const uint32_t BhU = smem_u32(Bh);

    float c[2][4][4];
    #pragma unroll
    for (int mi = 0; mi < 2; mi++)
        #pragma unroll
        for (int nb = 0; nb < 4; nb++)
            #pragma unroll
            for (int q = 0; q < 4; q++) c[mi][nb][q] = 0.0f;

    for (int kc = 0; kc < 1024; kc += 64) {
        __syncthreads();
        #pragma unroll
        for (int it = 0; it < 4; it++) {
            int idx = it * 256 + tid;
            int row = idx >> 3, k8 = idx & 7;
            size_t src = (size_t)(m0 + row) * 1024 + kc + k8 * 8;
            *(uint4*)&Ah[row * 72 + k8 * 8] = *(const uint4*)&g_Xh[src];
        }
        {
            int idx = tid;
            int row = idx >> 3, k8 = idx & 7;
            size_t src = (size_t)(n0 + row) * 1024 + kc + k8 * 8;
            *(uint4*)&Bh[row * 72 + k8 * 8] = *(const uint4*)&g_Uth[src];
            idx = 256 + tid;
            row = idx >> 3; k8 = idx & 7;
            src = (size_t)(n0 + row) * 1024 + kc + k8 * 8;
            *(uint4*)&Bh[row * 72 + k8 * 8] = *(const uint4*)&g_Uth[src];
        }
        __syncthreads();

        #pragma unroll
        for (int k16 = 0; k16 < 4; k16++) {
            const int kcol = k16 * 16;
            uint32_t ah[2][4], bh[2][4];
            #pragma unroll
            for (int mi = 0; mi < 2; mi++) {
                uint32_t off = (uint32_t)(((mi2 * 32 + mi * 16 + (lane & 15)) * 72
                                           + kcol + (lane >> 4) * 8) * 2);
                LDMATRIX_X4(ah[mi][0], ah[mi][1], ah[mi][2], ah[mi][3], AhU + off);
            }
            #pragma unroll
            for (int nb2 = 0; nb2 < 2; nb2++) {
                int rowb = nh2 * 32 + nb2 * 16 + ((lane >> 4) << 3) + (lane & 7);
                int koff = kcol + ((lane >> 3) & 1) * 8;
                uint32_t off = (uint32_t)((rowb * 72 + koff) * 2);
                LDMATRIX_X4(bh[nb2][0], bh[nb2][1], bh[nb2][2], bh[nb2][3], BhU + off);
            }
            #pragma unroll
            for (int mi = 0; mi < 2; mi++)
                #pragma unroll
                for (int nb = 0; nb < 4; nb++) {
                    uint32_t b0 = bh[nb >> 1][(nb & 1) * 2];
                    uint32_t b1 = bh[nb >> 1][(nb & 1) * 2 + 1];
                    MMA_FP16(c[mi][nb], ah[mi][0], ah[mi][1], ah[mi][2], ah[mi][3], b0, b1);
                }
        }
    }

    #pragma unroll
    for (int mi = 0; mi < 2; mi++)
        #pragma unroll
        for (int nb = 0; nb < 4; nb++) {
            int e_loc = nh2 * 32 + nb * 8 + (lane & 3) * 2;
            float bias0 = bp[(n0 & 1023) + e_loc];
            float bias1 = bp[(n0 & 1023) + e_loc + 1];
            #pragma unroll
            for (int h = 0; h < 2; h++) {
                int m = m0 + mi2 * 32 + mi * 16 + (lane >> 2) + h * 8;
                int s = m & 511, b = m >> 9;
                float2 v = {c[mi][nb][h * 2] + bias0, c[mi][nb][h * 2 + 1] + bias1};
                *(float2*)&g_xp[((size_t)s * BB + b) * EE + n0 + e_loc] = v;
            }
        }
}

// =====================================================================
// Kernel 2: HMMA recurrence, warp-specialized.
// 128 persistent CTAs x 512 threads. CTA owns 32 z-cols (4 gates x 8 d).
// Warps 0-7  = consumers: warp ks does K-chunk [128ks,128ks+128), N=32.
// Warps 8-15 = producers: warp fills chunk ks, runs gates tail.
// Pair barrier 1+ks (64 thr) called twice/step (phase0/phase1): producer
// fills phase1 while consumer runs MMA on phase0.
// SMEM: h [32][1032] half (66048) + red [2 par][8 ks][32 j][33 b] f32 (67584)
// =====================================================================
#define H_STRIDE 1032
#define RED_PAR  (8 * 32 * 33)
#define REC_SMEM_BYTES (32 * H_STRIDE * 2 + 2 * RED_PAR * 4)

__global__ void __launch_bounds__(512, 1) lstm_rec_mma(
    const float* __restrict__ Wi, const float* __restrict__ Wf,
    const float* __restrict__ Wo, const float* __restrict__ Wg,
    float* __restrict__ out)
{
    extern __shared__ char sm[];
    __half* sH = (__half*)sm;                                  // [32][1032]
    float* red = (float*)(sm + 32 * H_STRIDE * 2);             // [2][8][32][33]

    const int tid  = threadIdx.x;
    const int wid  = tid >> 5;
    const int lane = tid & 31;
    const int d0   = blockIdx.x * 8;
    const uint32_t sH_u = smem_u32(sH);

    // ---- init: zero h_{-1} (buffer 1) slice (producers = 256 threads), flag ----
    if (tid >= 256) {
        int zgb = tid & 31, zgdl = (tid >> 5) & 7;
        g_hH[1][zgb * DD + d0 + zgdl] = __float2half(0.0f);
    }
    if (tid == 0) g_flag[blockIdx.x][0] = 0ULL;

    __threadfence();
    __syncthreads();

    // ---- initial full grid barrier (monotonic counter, epoch-derived) ----
    if (tid == 0) {
        u64 old = atomicAdd(&g_bar, 1ULL);
        u64 bs  = old - (old & (u64)(NBLK - 1));
        u64 tgt = bs + NBLK;
        while (*((volatile u64*)&g_bar) < tgt) { }
        __threadfence();
    }
    __syncthreads();

    if (wid < 8) {
        // ================= CONSUMER: MMA warps =================
        const int ks = wid;
        const int kbase = ks << 7;

        // W fragments: j = ni*8 + (lane>>2), gate = ni
        uint32_t Wfr[8][4][2];
        {
            const float* Wm[4] = {Wi, Wf, Wo, Wg};
            #pragma unroll
            for (int k16 = 0; k16 < 8; k16++)
                #pragma unroll
                for (int ni = 0; ni < 4; ni++)
                    #pragma unroll
                    for (int r = 0; r < 2; r++) {
                        int k0 = kbase + k16 * 16 + (lane & 3) * 2 + r * 8;
                        const float* wp = Wm[ni] + (size_t)k0 * 1024 + d0 + (lane >> 2);
                        Wfr[k16][ni][r] = pack_hf2(__ldg(wp), __ldg(wp + 1024));
                    }
        }

        for (int s = 0; s < SS; s++) {
            const int wpar = s & 1;
            float c[2][4][4];
            #pragma unroll
            for (int mi = 0; mi < 2; mi++)
                #pragma unroll
                for (int ni = 0; ni < 4; ni++)
                    #pragma unroll
                    for (int q = 0; q < 4; q++) c[mi][ni][q] = 0.0f;

            #pragma unroll
            for (int ph = 0; ph < 2; ph++) {
                asm volatile("bar.sync %0, 64;" :: "r"(1 + ks) : "memory");
                #pragma unroll
                for (int kq = 0; kq < 4; kq++) {
                    const int k16 = ph * 4 + kq;
                    const int kcol = kbase + k16 * 16;
                    #pragma unroll
                    for (int mi = 0; mi < 2; mi++) {
                        uint32_t off = (uint32_t)(((mi * 16 + (lane & 15)) * H_STRIDE
                                                   + kcol + (lane >> 4) * 8) * 2);
                        uint32_t a0, a1, a2, a3;
                        LDMATRIX_X4(a0, a1, a2, a3, sH_u + off);
                        #pragma unroll
                        for (int ni = 0; ni < 4; ni++)
                            MMA_FP16(c[mi][ni], a0, a1, a2, a3,
                                     Wfr[k16][ni][0], Wfr[k16][ni][1]);
                    }
                }
            }

            // store partials: red[wpar][ks][j][33b], scalar stores
            {
                float* rb = red + wpar * RED_PAR + ks * (32 * 33);
                #pragma unroll
                for (int mi = 0; mi < 2; mi++)
                    #pragma unroll
                    for (int ni = 0; ni < 4; ni++) {
                        int row0 = mi * 16 + (lane >> 2);
                        int col0 = ni * 8 + (lane & 3) * 2;
                        rb[col0 * 33 + row0]           = c[mi][ni][0];
                        rb[(col0 + 1) * 33 + row0]     = c[mi][ni][1];
                        rb[col0 * 33 + row0 + 8]       = c[mi][ni][2];
                        rb[(col0 + 1) * 33 + row0 + 8] = c[mi][ni][3];
                    }
            }
            __syncthreads();
        }
    } else {
        // ================= PRODUCER: fill + gates warps =================
        const int ks = wid - 8;
        const int kbase = ks << 7;
        const int fk  = lane & 7;          // 16B chunk within 64-col phase
        const int fbq = lane >> 3;         // b-subrow 0..3
        const u64* poll0 = &g_flag[16 * ks + fk][0];
        const u64* poll1 = &g_flag[16 * ks + 8 + fk][0];
        const int gb  = tid & 31;
        const int gdl = (tid >> 5) & 7;
        float c_reg = 0.0f;

        for (int s = 0; s < SS; s++) {
            const int rpar = (s + 1) & 1;
            const int wpar = s & 1;

            // xp prefetch
            const float* xpp = g_xp + ((size_t)s * BB + gb) * EE + d0 + gdl;
            float xp0 = __ldg(xpp);
            float xp1 = __ldg(xpp + 1024);
            float xp2 = __ldg(xpp + 2048);
            float xp3 = __ldg(xpp + 3072);

            const __half* srcH = g_hH[rpar];

            // ---- phase 0: poll + fill cols [kbase, kbase+64) ----
            {
                u64 v;
                do {
                    asm volatile("ld.acquire.gpu.global.u64 %0, [%1];"
                                 : "=l"(v) : "l"(poll0));
                } while (v < (u64)s);
            }
            {
                uint4 v[8];
                #pragma unroll
                for (int it = 0; it < 8; it++) {
                    int b = it * 4 + fbq;
                    v[it] = __ldcg((const uint4*)(srcH + b * DD + kbase + fk * 8));
                }
                #pragma unroll
                for (int it = 0; it < 8; it++) {
                    int b = it * 4 + fbq;
                    *(uint4*)(sH + b * H_STRIDE + kbase + fk * 8) = v[it];
                }
            }
            asm volatile("bar.sync %0, 64;" :: "r"(1 + ks) : "memory");

            // ---- phase 1: poll + fill cols [kbase+64, kbase+128) ----
            {
                u64 v;
                do {
                    asm volatile("ld.acquire.gpu.global.u64 %0, [%1];"
                                 : "=l"(v) : "l"(poll1));
                } while (v < (u64)s);
            }
            {
                uint4 v[8];
                #pragma unroll
                for (int it = 0; it < 8; it++) {
                    int b = it * 4 + fbq;
                    v[it] = __ldcg((const uint4*)(srcH + b * DD + kbase + 64 + fk * 8));
                }
                #pragma unroll
                for (int it = 0; it < 8; it++) {
                    int b = it * 4 + fbq;
                    *(uint4*)(sH + b * H_STRIDE + kbase + 64 + fk * 8) = v[it];
                }
            }
            asm volatile("bar.sync %0, 64;" :: "r"(1 + ks) : "memory");

            __syncthreads();   // consumers finished red[wpar] for step s

            // ---- gates tail ----
            {
                const float* rp = red + wpar * RED_PAR;
                float z0 = xp0, z1 = xp1, z2 = xp2, z3 = xp3;
                #pragma unroll
                for (int kk = 0; kk < 8; kk++) {
                    const float* rb = rp + kk * (32 * 33);
                    z0 += rb[(0 * 8 + gdl) * 33 + gb];
                    z1 += rb[(1 * 8 + gdl) * 33 + gb];
                    z2 += rb[(2 * 8 + gdl) * 33 + gb];
                    z3 += rb[(3 * 8 + gdl) * 33 + gb];
                }
                float it = sigf(z0), ft = sigf(z1), ot = sigf(z2);
                float gt = tanhf_fast(z3);
                float ct = sigf(ft * c_reg + it * gt);   // nonstandard cell (matches ref)
                float ht = tanhf_fast(ct) * ot;
                c_reg = ct;
                out[((size_t)gb * SS + s) * DD + d0 + gdl] = ht;
                g_hH[wpar][gb * DD + d0 + gdl] = __float2half_rn(ht);
            }

            // gates-group barrier (warps 8-15 = 256 threads), publish flag
            asm volatile("bar.sync 9, 256;" ::: "memory");
            if (tid == 256) {
                asm volatile("st.release.gpu.global.u64 [%0], %1;"
                             :: "l"(&g_flag[blockIdx.x][0]), "l"((u64)(s + 1)) : "memory");
            }
        }
    }
}

// =====================================================================
// Input order: 0:seq, 1:Ui, 2:Wi, 3:Uf, 4:Wf, 5:Uo, 6:Wo, 7:Ug, 8:Wg,
//              9:bi, 10:bf, 11:bo, 12:bg
// =====================================================================
extern "C" void kernel_launch(void* const* d_in, const int* in_sizes, int n_in,
                              void* d_out, int out_size)
{
    const float* X  = (const float*)d_in[0];
    const float* Ui = (const float*)d_in[1];
    const float* Wi = (const float*)d_in[2];
    const float* Uf = (const float*)d_in[3];
    const float* Wf = (const float*)d_in[4];
    const float* Uo = (const float*)d_in[5];
    const float* Wo = (const float*)d_in[6];
    const float* Ug = (const float*)d_in[7];
    const float* Wg = (const float*)d_in[8];
    const float* bi = (const float*)d_in[9];
    const float* bf = (const float*)d_in[10];
    const float* bo = (const float*)d_in[11];
    const float* bg = (const float*)d_in[12];
    float* out = (float*)d_out;

    // Prep: X -> fp16, transpose U -> fp16
    splitX_kernel<<<(BB * SS * DD) / (256 * 4), 256>>>(X);
    dim3 gt(32, 32, 4);
    transU_kernel<<<gt, 256>>>(Ui, Uf, Uo, Ug);

    // x_proj GEMM (HMMA fp16)
    cudaFuncSetAttribute(xproj_mma,
                         cudaFuncAttributeMaxDynamicSharedMemorySize, XJ_SMEM);
    dim3 g1(EE / 64, (BB * SS) / 128);   // (64, 128)
    xproj_mma<<<g1, 256, XJ_SMEM>>>(bi, bf, bo, bg);

    // Recurrence (HMMA fp16, warp-specialized, flag-sync)
    cudaFuncSetAttribute(lstm_rec_mma,
                         cudaFuncAttributeMaxDynamicSharedMemorySize, REC_SMEM_BYTES);
    lstm_rec_mma<<<NBLK, 512, REC_SMEM_BYTES>>>(Wi, Wf, Wo, Wg, out);
}

// round 16
// speedup vs baseline: 3.2058x; 1.0151x over previous
#include <cuda_runtime.h>
#include <cuda_fp16.h>
#include <math.h>
#include <stdint.h>

// Problem constants
#define BB   32
#define SS   512
#define DD   1024
#define EE   4096          // 4*D
#define NBLK 128           // recurrence CTAs (all co-resident, 1/SM)

typedef unsigned long long u64;

// ---------- scratch (static __device__: no runtime allocation) ----------
__device__ __align__(16) float g_xp[(size_t)SS * BB * EE];       // x_proj [s][b][e]
__device__ __align__(16) __half g_Xh [(size_t)BB * SS * DD];     // X fp16
__device__ __align__(16) __half g_Uth[(size_t)EE * DD];          // U^T fp16 [e][k]
__device__ __align__(16) __half g_hT[2][DD * BB];                // h fp16 TRANSPOSED [par][d][b]
__device__ u64 g_bar;                                            // init barrier (monotonic)
__device__ u64 g_flag[NBLK][16];                                 // per-CTA step flags, 128B pad

__device__ __forceinline__ uint32_t smem_u32(const void* p) {
    uint32_t a;
    asm("{ .reg .u64 t; cvta.to.shared.u64 t, %1; cvt.u32.u64 %0, t; }" : "=r"(a) : "l"(p));
    return a;
}

__device__ __forceinline__ float sigf(float x) {
    float e = __expf(-x);
    float y; asm("rcp.approx.f32 %0, %1;" : "=f"(y) : "f"(1.0f + e));
    return y;
}

__device__ __forceinline__ float tanhf_fast(float x) {
    float e = __expf(2.0f * x);
    return 1.0f - __fdividef(2.0f, e + 1.0f);   // exact limits at +/-inf
}

__device__ __forceinline__ uint32_t pack_hf2(float a, float b) {
    __half h0 = __float2half_rn(a), h1 = __float2half_rn(b);
    uint16_t u0, u1;
    memcpy(&u0, &h0, 2); memcpy(&u1, &h1, 2);
    return (uint32_t)u0 | ((uint32_t)u1 << 16);
}

#define LDMATRIX_X4(a0, a1, a2, a3, addr) \
    asm volatile("ldmatrix.sync.aligned.m8n8.x4.shared.b16 {%0,%1,%2,%3}, [%4];" \
                 : "=r"(a0), "=r"(a1), "=r"(a2), "=r"(a3) : "r"(addr))

#define LDMATRIX_X4_TRANS(a0, a1, a2, a3, addr) \
    asm volatile("ldmatrix.sync.aligned.m8n8.x4.trans.shared.b16 {%0,%1,%2,%3}, [%4];" \
                 : "=r"(a0), "=r"(a1), "=r"(a2), "=r"(a3) : "r"(addr))

#define MMA_FP16(c, a0, a1, a2, a3, b0, b1) \
    asm volatile("mma.sync.aligned.m16n8k16.row.col.f32.f16.f16.f32 " \
                 "{%0,%1,%2,%3}, {%4,%5,%6,%7}, {%8,%9}, {%0,%1,%2,%3};" \
                 : "+f"((c)[0]), "+f"((c)[1]), "+f"((c)[2]), "+f"((c)[3]) \
                 : "r"(a0), "r"(a1), "r"(a2), "r"(a3), "r"(b0), "r"(b1))

// =====================================================================
// Prep 1: X (fp32) -> fp16, same layout (m=b*512+s rows)
// =====================================================================
__global__ void __launch_bounds__(256) splitX_kernel(const float* __restrict__ X)
{
    size_t i = ((size_t)blockIdx.x * 256 + threadIdx.x) * 4;
    float4 v = *(const float4*)(X + i);
    __half2 p01, p23;
    p01.x = __float2half_rn(v.x); p01.y = __float2half_rn(v.y);
    p23.x = __float2half_rn(v.z); p23.y = __float2half_rn(v.w);
    *(__half2*)(g_Xh + i)     = p01;
    *(__half2*)(g_Xh + i + 2) = p23;
}

// =====================================================================
// Prep 2: transpose U -> fp16: g_Uth[e=gate*1024+col][k] = Ugate[k][col]
// =====================================================================
__global__ void __launch_bounds__(256) transU_kernel(
    const float* __restrict__ Ui, const float* __restrict__ Uf,
    const float* __restrict__ Uo, const float* __restrict__ Ug)
{
    __shared__ float t[32][33];
    const int gate = blockIdx.z;
    const float* U = (gate == 0) ? Ui : (gate == 1) ? Uf : (gate == 2) ? Uo : Ug;
    const int col0 = blockIdx.x * 32;
    const int k0   = blockIdx.y * 32;
    const int tx = threadIdx.x & 31, ty = threadIdx.x >> 5;

    #pragma unroll
    for (int rr = 0; rr < 4; rr++)
        t[ty + rr * 8][tx] = U[(size_t)(k0 + ty + rr * 8) * 1024 + col0 + tx];
    __syncthreads();
    #pragma unroll
    for (int rr = 0; rr < 4; rr++) {
        int c = ty + rr * 8;
        g_Uth[(size_t)(gate * 1024 + col0 + c) * 1024 + k0 + tx] =
            __float2half_rn(t[tx][c]);
    }
}

// =====================================================================
// Kernel 1: x_proj via HMMA fp16 (single pass). CTA 128m x 64n, 8 warps.
// =====================================================================
#define XJ_SMEM ((128 + 64) * 72 * 2)

__global__ void __launch_bounds__(256) xproj_mma(
    const float* __restrict__ bi, const float* __restrict__ bf_,
    const float* __restrict__ bo, const float* __restrict__ bg)
{
    extern __shared__ __half xsm[];
    __half* Ah = xsm;                 // [128][72]
    __half* Bh = Ah + 128 * 72;       // [64][72]

    const int tid  = threadIdx.x;
    const int wid  = tid >> 5;
    const int lane = tid & 31;
    const int n0   = blockIdx.x * 64;
    const int m0   = blockIdx.y * 128;
    const int gate = n0 >> 10;
    const float* bp = (gate == 0) ? bi : (gate == 1) ? bf_ : (gate == 2) ? bo : bg;

    const int mi2 = wid & 3;
    const int nh2 = wid >> 2;

    const uint32_t AhU = smem_u32(Ah);
    const uint32_t BhU = smem_u32(Bh);

    float c[2][4][4];
    #pragma unroll
    for (int mi = 0; mi < 2; mi++)
        #pragma unroll
        for (int nb = 0; nb < 4; nb++)
            #pragma unroll
            for (int q = 0; q < 4; q++) c[mi][nb][q] = 0.0f;

    for (int kc = 0; kc < 1024; kc += 64) {
        __syncthreads();
        #pragma unroll
        for (int it = 0; it < 4; it++) {
            int idx = it * 256 + tid;
            int row = idx >> 3, k8 = idx & 7;
            size_t src = (size_t)(m0 + row) * 1024 + kc + k8 * 8;
            *(uint4*)&Ah[row * 72 + k8 * 8] = *(const uint4*)&g_Xh[src];
        }
        {
            int idx = tid;
            int row = idx >> 3, k8 = idx & 7;
            size_t src = (size_t)(n0 + row) * 1024 + kc + k8 * 8;
            *(uint4*)&Bh[row * 72 + k8 * 8] = *(const uint4*)&g_Uth[src];
            idx = 256 + tid;
            row = idx >> 3; k8 = idx & 7;
            src = (size_t)(n0 + row) * 1024 + kc + k8 * 8;
            *(uint4*)&Bh[row * 72 + k8 * 8] = *(const uint4*)&g_Uth[src];
        }
        __syncthreads();

        #pragma unroll
        for (int k16 = 0; k16 < 4; k16++) {
            const int kcol = k16 * 16;
            uint32_t ah[2][4], bh[2][4];
            #pragma unroll
            for (int mi = 0; mi < 2; mi++) {
                uint32_t off = (uint32_t)(((mi2 * 32 + mi * 16 + (lane & 15)) * 72
                                           + kcol + (lane >> 4) * 8) * 2);
                LDMATRIX_X4(ah[mi][0], ah[mi][1], ah[mi][2], ah[mi][3], AhU + off);
            }
            #pragma unroll
            for (int nb2 = 0; nb2 < 2; nb2++) {
                int rowb = nh2 * 32 + nb2 * 16 + ((lane >> 4) << 3) + (lane & 7);
                int koff = kcol + ((lane >> 3) & 1) * 8;
                uint32_t off = (uint32_t)((rowb * 72 + koff) * 2);
                LDMATRIX_X4(bh[nb2][0], bh[nb2][1], bh[nb2][2], bh[nb2][3], BhU + off);
            }
            #pragma unroll
            for (int mi = 0; mi < 2; mi++)
                #pragma unroll
                for (int nb = 0; nb < 4; nb++) {
                    uint32_t b0 = bh[nb >> 1][(nb & 1) * 2];
                    uint32_t b1 = bh[nb >> 1][(nb & 1) * 2 + 1];
                    MMA_FP16(c[mi][nb], ah[mi][0], ah[mi][1], ah[mi][2], ah[mi][3], b0, b1);
                }
        }
    }

    #pragma unroll
    for (int mi = 0; mi < 2; mi++)
        #pragma unroll
        for (int nb = 0; nb < 4; nb++) {
            int e_loc = nh2 * 32 + nb * 8 + (lane & 3) * 2;
            float bias0 = bp[(n0 & 1023) + e_loc];
            float bias1 = bp[(n0 & 1023) + e_loc + 1];
            #pragma unroll
            for (int h = 0; h < 2; h++) {
                int m = m0 + mi2 * 32 + mi * 16 + (lane >> 2) + h * 8;
                int s = m & 511, b = m >> 9;
                float2 v = {c[mi][nb][h * 2] + bias0, c[mi][nb][h * 2 + 1] + bias1};
                *(float2*)&g_xp[((size_t)s * BB + b) * EE + n0 + e_loc] = v;
            }
        }
}

// =====================================================================
// Kernel 2: HMMA recurrence, warp-specialized, TRANSPOSED h exchange.
// 128 persistent CTAs x 512 threads. CTA owns 32 z-cols (4 gates x 8 d).
// h lives in global as hT[d][b]: producer warp 8+g stores one contiguous
// 64B line (d0+g, all b); consumer chunk ks = rows [128ks,128ks+128) =
// one contiguous 8KB stream. SMEM sT[k][b], stride 40 halves (80B) ->
// ldmatrix.trans row addresses conflict-free; A-frags via x4.trans.
// SMEM: sT 1024*40*2 = 81920 + red [2][8][32][33] f32 = 67584 -> 149504
// =====================================================================
#define T_STRIDE 40
#define RED_PAR  (8 * 32 * 33)
#define REC_SMEM_BYTES (1024 * T_STRIDE * 2 + 2 * RED_PAR * 4)

__global__ void __launch_bounds__(512, 1) lstm_rec_mma(
    const float* __restrict__ Wi, const float* __restrict__ Wf,
    const float* __restrict__ Wo, const float* __restrict__ Wg,
    float* __restrict__ out)
{
    extern __shared__ char sm[];
    __half* sT = (__half*)sm;                                  // [1024][40]
    float* red = (float*)(sm + 1024 * T_STRIDE * 2);           // [2][8][32][33]

    const int tid  = threadIdx.x;
    const int wid  = tid >> 5;
    const int lane = tid & 31;
    const int d0   = blockIdx.x * 8;
    const uint32_t sT_u = smem_u32(sT);

    // ---- init: zero h_{-1} (buffer 1) slice (producers), reset flag ----
    if (tid >= 256) {
        int zgb = tid & 31, zgdl = (tid >> 5) & 7;
        g_hT[1][(d0 + zgdl) * 32 + zgb] = __float2half(0.0f);
    }
    if (tid == 0) g_flag[blockIdx.x][0] = 0ULL;

    __threadfence();
    __syncthreads();

    // ---- initial full grid barrier (monotonic counter, epoch-derived) ----
    if (tid == 0) {
        u64 old = atomicAdd(&g_bar, 1ULL);
        u64 bs  = old - (old & (u64)(NBLK - 1));
        u64 tgt = bs + NBLK;
        while (*((volatile u64*)&g_bar) < tgt) { }
        __threadfence();
    }
    __syncthreads();

    if (wid < 8) {
        // ================= CONSUMER: MMA warps =================
        const int ks = wid;
        const int kbase = ks << 7;

        // W fragments: j = ni*8 + (lane>>2), gate = ni
        uint32_t Wfr[8][4][2];
        {
            const float* Wm[4] = {Wi, Wf, Wo, Wg};
            #pragma unroll
            for (int k16 = 0; k16 < 8; k16++)
                #pragma unroll
                for (int ni = 0; ni < 4; ni++)
                    #pragma unroll
                    for (int r = 0; r < 2; r++) {
                        int k0 = kbase + k16 * 16 + (lane & 3) * 2 + r * 8;
                        const float* wp = Wm[ni] + (size_t)k0 * 1024 + d0 + (lane >> 2);
                        Wfr[k16][ni][r] = pack_hf2(__ldg(wp), __ldg(wp + 1024));
                    }
        }

        // A-fragment ldmatrix.trans addressing (constant per lane):
        // koff_lane = khalf + row, mcol = mi*16 + mhalf
        const int a_krow = ((lane >> 4) & 1) * 8 + (lane & 7);
        const int a_mh   = ((lane >> 3) & 1) * 8;

        for (int s = 0; s < SS; s++) {
            const int wpar = s & 1;
            float c[2][4][4];
            #pragma unroll
            for (int mi = 0; mi < 2; mi++)
                #pragma unroll
                for (int ni = 0; ni < 4; ni++)
                    #pragma unroll
                    for (int q = 0; q < 4; q++) c[mi][ni][q] = 0.0f;

            #pragma unroll
            for (int ph = 0; ph < 2; ph++) {
                asm volatile("bar.sync %0, 64;" :: "r"(1 + ks) : "memory");
                #pragma unroll
                for (int kq = 0; kq < 4; kq++) {
                    const int k16 = ph * 4 + kq;
                    const int krow = kbase + k16 * 16 + a_krow;
                    #pragma unroll
                    for (int mi = 0; mi < 2; mi++) {
                        uint32_t off = (uint32_t)((krow * T_STRIDE
                                                   + mi * 16 + a_mh) * 2);
                        uint32_t a0, a1, a2, a3;
                        LDMATRIX_X4_TRANS(a0, a1, a2, a3, sT_u + off);
                        #pragma unroll
                        for (int ni = 0; ni < 4; ni++)
                            MMA_FP16(c[mi][ni], a0, a1, a2, a3,
                                     Wfr[k16][ni][0], Wfr[k16][ni][1]);
                    }
                }
            }

            // store partials: red[wpar][ks][j][33b], scalar stores
            {
                float* rb = red + wpar * RED_PAR + ks * (32 * 33);
                #pragma unroll
                for (int mi = 0; mi < 2; mi++)
                    #pragma unroll
                    for (int ni = 0; ni < 4; ni++) {
                        int row0 = mi * 16 + (lane >> 2);
                        int col0 = ni * 8 + (lane & 3) * 2;
                        rb[col0 * 33 + row0]           = c[mi][ni][0];
                        rb[(col0 + 1) * 33 + row0]     = c[mi][ni][1];
                        rb[col0 * 33 + row0 + 8]       = c[mi][ni][2];
                        rb[(col0 + 1) * 33 + row0 + 8] = c[mi][ni][3];
                    }
            }
            __syncthreads();
        }
    } else {
        // ================= PRODUCER: fill + gates warps =================
        const int ks = wid - 8;
        const int kbase = ks << 7;
        const int gb  = tid & 31;
        const int gdl = (tid >> 5) & 7;
        // poll: lane polls flag of producer (lane&7) of current phase;
        // warp-converged loop exit + release-to-L2 + __ldcg => safe for all 8
        const u64* poll0 = &g_flag[16 * ks + (lane & 7)][0];
        const u64* poll1 = &g_flag[16 * ks + 8 + (lane & 7)][0];
        float c_reg = 0.0f;

        for (int s = 0; s < SS; s++) {
            const int rpar = (s + 1) & 1;
            const int wpar = s & 1;

            // xp prefetch
            const float* xpp = g_xp + ((size_t)s * BB + gb) * EE + d0 + gdl;
            float xp0 = __ldg(xpp);
            float xp1 = __ldg(xpp + 1024);
            float xp2 = __ldg(xpp + 2048);
            float xp3 = __ldg(xpp + 3072);

            const __half* srcT = g_hT[rpar];

            // ---- two fill phases: 64 hT rows (4KB contiguous) each ----
            #pragma unroll
            for (int ph = 0; ph < 2; ph++) {
                {
                    const u64* pf = ph ? poll1 : poll0;
                    u64 v;
                    do {
                        asm volatile("ld.acquire.gpu.global.u64 %0, [%1];"
                                     : "=l"(v) : "l"(pf));
                    } while (v < (u64)s);
                    __syncwarp();
                }
                const __half* src = srcT + kbase * 32 + ph * 2048;
                uint4 w[8];
                #pragma unroll
                for (int it = 0; it < 8; it++)
                    w[it] = __ldcg((const uint4*)(src + (it * 32 + lane) * 8));
                #pragma unroll
                for (int it = 0; it < 8; it++) {
                    int u = it * 32 + lane;
                    int row = kbase + ph * 64 + (u >> 2);
                    *(uint4*)(sT + (size_t)row * T_STRIDE + (u & 3) * 8) = w[it];
                }
                asm volatile("bar.sync %0, 64;" :: "r"(1 + ks) : "memory");
            }

            __syncthreads();   // consumers finished red[wpar] for step s

            // ---- gates tail ----
            {
                const float* rp = red + wpar * RED_PAR;
                float z0 = xp0, z1 = xp1, z2 = xp2, z3 = xp3;
                #pragma unroll
                for (int kk = 0; kk < 8; kk++) {
                    const float* rb = rp + kk * (32 * 33);
                    z0 += rb[(0 * 8 + gdl) * 33 + gb];
                    z1 += rb[(1 * 8 + gdl) * 33 + gb];
                    z2 += rb[(2 * 8 + gdl) * 33 + gb];
                    z3 += rb[(3 * 8 + gdl) * 33 + gb];
                }
                float it = sigf(z0), ft = sigf(z1), ot = sigf(z2);
                float gt = tanhf_fast(z3);
                float ct = sigf(ft * c_reg + it * gt);   // nonstandard cell (matches ref)
                float ht = tanhf_fast(ct) * ot;
                c_reg = ct;
                out[((size_t)gb * SS + s) * DD + d0 + gdl] = ht;
                // TRANSPOSED h store: warp 8+gdl writes 64B contiguous
                g_hT[wpar][(d0 + gdl) * 32 + gb] = __float2half_rn(ht);
            }

            // gates-group barrier (warps 8-15 = 256 threads), publish flag
            asm volatile("bar.sync 9, 256;" ::: "memory");
            if (tid == 256) {
                asm volatile("st.release.gpu.global.u64 [%0], %1;"
                             :: "l"(&g_flag[blockIdx.x][0]), "l"((u64)(s + 1)) : "memory");
            }
        }
    }
}

// =====================================================================
// Input order: 0:seq, 1:Ui, 2:Wi, 3:Uf, 4:Wf, 5:Uo, 6:Wo, 7:Ug, 8:Wg,
//              9:bi, 10:bf, 11:bo, 12:bg
// =====================================================================
extern "C" void kernel_launch(void* const* d_in, const int* in_sizes, int n_in,
                              void* d_out, int out_size)
{
    const float* X  = (const float*)d_in[0];
    const float* Ui = (const float*)d_in[1];
    const float* Wi = (const float*)d_in[2];
    const float* Uf = (const float*)d_in[3];
    const float* Wf = (const float*)d_in[4];
    const float* Uo = (const float*)d_in[5];
    const float* Wo = (const float*)d_in[6];
    const float* Ug = (const float*)d_in[7];
    const float* Wg = (const float*)d_in[8];
    const float* bi = (const float*)d_in[9];
    const float* bf = (const float*)d_in[10];
    const float* bo = (const float*)d_in[11];
    const float* bg = (const float*)d_in[12];
    float* out = (float*)d_out;

    // Prep: X -> fp16, transpose U -> fp16
    splitX_kernel<<<(BB * SS * DD) / (256 * 4), 256>>>(X);
    dim3 gt(32, 32, 4);
    transU_kernel<<<gt, 256>>>(Ui, Uf, Uo, Ug);

    // x_proj GEMM (HMMA fp16)
    cudaFuncSetAttribute(xproj_mma,
                         cudaFuncAttributeMaxDynamicSharedMemorySize, XJ_SMEM);
    dim3 g1(EE / 64, (BB * SS) / 128);   // (64, 128)
    xproj_mma<<<g1, 256, XJ_SMEM>>>(bi, bf, bo, bg);

    // Recurrence (HMMA fp16, warp-specialized, transposed h exchange)
    cudaFuncSetAttribute(lstm_rec_mma,
                         cudaFuncAttributeMaxDynamicSharedMemorySize, REC_SMEM_BYTES);
    lstm_rec_mma<<<NBLK, 512, REC_SMEM_BYTES>>>(Wi, Wf, Wo, Wg, out);
}